// round 1
// baseline (speedup 1.0000x reference)
#include <cuda_runtime.h>
#include <cuda_bf16.h>
#include <math.h>

// ----------------------------------------------------------------------------
// LlamaAttention + H2O mask, fp32 baseline.
// B=1, S=2048, HID=4096, NH=32, NKV=8, HD=128, GROUPS=4
// heavy_budget = recent_budget = 204
// Outputs (concatenated in d_out): attn_output [S, HID] fp32, then
// attention_masks_next [NH, S+1] fp32 (offset computed as out_size - NH*(S+1)).
// ----------------------------------------------------------------------------

#define S_LEN   2048
#define HID     4096
#define NH      32
#define NKV     8
#define HD      128
#define HB      204   // heavy budget
#define RB      204   // recent budget
#define SEL     (S_LEN - RB)   // 1844

// Scratch (static __device__ arrays; no runtime allocation)
__device__ float g_Q [S_LEN * HID];              // 32 MB
__device__ float g_K [S_LEN * NKV * HD];         // 8 MB
__device__ float g_V [S_LEN * NKV * HD];         // 8 MB
__device__ float g_S [(size_t)NH * S_LEN * S_LEN]; // 512 MB scores/attn
__device__ float g_O [S_LEN * HID];              // 32 MB (context pre-Wo)
__device__ float g_CS[NH * S_LEN];               // column sums

// ============================================================================
// Tiled SGEMM: C = alpha * A * B^T
// A: M x K row-major (lda), B: N x K row-major (ldb), C: M x N row-major (ldc)
// grid: (N/128, M/128, nHeads). Per-head pointer offsets via head strides.
// causal=1: skip blocks with bx > by (upper triangle).
// ============================================================================
__global__ __launch_bounds__(256)
void gemm_abt(const float* __restrict__ A, const float* __restrict__ B,
              float* __restrict__ C,
              int K, int lda, int ldb, int ldc,
              long aHS, long bHS, long cHS, int bShift,
              float alpha, int causal)
{
    const int h  = blockIdx.z;
    A += (long)h * aHS;
    B += (long)(h >> bShift) * bHS;
    C += (long)h * cHS;
    const int bx = blockIdx.x, by = blockIdx.y;
    if (causal && bx > by) return;

    __shared__ float As[16][128];
    __shared__ float Bs[16][128];

    const int tid = threadIdx.x;        // 0..255
    const int tx  = tid & 15;           // col group
    const int ty  = tid >> 4;           // row group

    float acc[8][8];
#pragma unroll
    for (int i = 0; i < 8; i++)
#pragma unroll
        for (int j = 0; j < 8; j++) acc[i][j] = 0.0f;

    const int lrow = tid >> 2;          // 0..63
    const int lcol = (tid & 3) * 4;     // 0,4,8,12

    const float* Ab = A + (long)(by * 128) * lda;
    const float* Bb = B + (long)(bx * 128) * ldb;

    for (int kk = 0; kk < K; kk += 16) {
#pragma unroll
        for (int r = 0; r < 2; r++) {
            const int row = lrow + r * 64;
            float4 va = *(const float4*)(Ab + (long)row * lda + kk + lcol);
            As[lcol + 0][row] = va.x;
            As[lcol + 1][row] = va.y;
            As[lcol + 2][row] = va.z;
            As[lcol + 3][row] = va.w;
            float4 vb = *(const float4*)(Bb + (long)row * ldb + kk + lcol);
            Bs[lcol + 0][row] = vb.x;
            Bs[lcol + 1][row] = vb.y;
            Bs[lcol + 2][row] = vb.z;
            Bs[lcol + 3][row] = vb.w;
        }
        __syncthreads();
#pragma unroll
        for (int k = 0; k < 16; k++) {
            float a[8], b[8];
#pragma unroll
            for (int i = 0; i < 8; i++) a[i] = As[k][ty * 8 + i];
#pragma unroll
            for (int j = 0; j < 8; j++) b[j] = Bs[k][tx * 8 + j];
#pragma unroll
            for (int i = 0; i < 8; i++)
#pragma unroll
                for (int j = 0; j < 8; j++) acc[i][j] += a[i] * b[j];
        }
        __syncthreads();
    }

#pragma unroll
    for (int i = 0; i < 8; i++) {
        float* Cr = C + (long)(by * 128 + ty * 8 + i) * ldc + bx * 128 + tx * 8;
#pragma unroll
        for (int j = 0; j < 8; j++) Cr[j] = alpha * acc[i][j];
    }
}

// ============================================================================
// Tiled SGEMM: C = alpha * A * B  (B row-major K x N)
// causal=1: limit K loop to (by+1)*128 (A is block-lower-triangular).
// ============================================================================
__global__ __launch_bounds__(256)
void gemm_ab(const float* __restrict__ A, const float* __restrict__ B,
             float* __restrict__ C,
             int K, int lda, int ldb, int ldc,
             long aHS, long bHS, long cHS, int bShift,
             float alpha, int causal)
{
    const int h  = blockIdx.z;
    A += (long)h * aHS;
    B += (long)(h >> bShift) * bHS;
    C += (long)h * cHS;
    const int bx = blockIdx.x, by = blockIdx.y;

    __shared__ float As[16][128];
    __shared__ float Bs[16][128];

    const int tid = threadIdx.x;
    const int tx  = tid & 15;
    const int ty  = tid >> 4;

    float acc[8][8];
#pragma unroll
    for (int i = 0; i < 8; i++)
#pragma unroll
        for (int j = 0; j < 8; j++) acc[i][j] = 0.0f;

    const int lrow  = tid >> 2;          // A loads
    const int lcol  = (tid & 3) * 4;
    const int brow  = tid >> 5;          // B loads: 0..7
    const int bcol4 = (tid & 31) * 4;    // 0..124

    const float* Ab = A + (long)(by * 128) * lda;

    int Keff = causal ? ((by + 1) * 128 < K ? (by + 1) * 128 : K) : K;

    for (int kk = 0; kk < Keff; kk += 16) {
#pragma unroll
        for (int r = 0; r < 2; r++) {
            const int row = lrow + r * 64;
            float4 va = *(const float4*)(Ab + (long)row * lda + kk + lcol);
            As[lcol + 0][row] = va.x;
            As[lcol + 1][row] = va.y;
            As[lcol + 2][row] = va.z;
            As[lcol + 3][row] = va.w;
            const int krow = brow + r * 8;
            float4 vb = *(const float4*)(B + (long)(kk + krow) * ldb + bx * 128 + bcol4);
            *(float4*)&Bs[krow][bcol4] = vb;
        }
        __syncthreads();
#pragma unroll
        for (int k = 0; k < 16; k++) {
            float a[8], b[8];
#pragma unroll
            for (int i = 0; i < 8; i++) a[i] = As[k][ty * 8 + i];
#pragma unroll
            for (int j = 0; j < 8; j++) b[j] = Bs[k][tx * 8 + j];
#pragma unroll
            for (int i = 0; i < 8; i++)
#pragma unroll
                for (int j = 0; j < 8; j++) acc[i][j] += a[i] * b[j];
        }
        __syncthreads();
    }

#pragma unroll
    for (int i = 0; i < 8; i++) {
        float* Cr = C + (long)(by * 128 + ty * 8 + i) * ldc + bx * 128 + tx * 8;
#pragma unroll
        for (int j = 0; j < 8; j++) Cr[j] = alpha * acc[i][j];
    }
}

// ============================================================================
// RoPE in place. X: [S, nh*HD] row-major. One thread per (s, h, d<64) pair.
// ============================================================================
__global__ void rope_kernel(float* __restrict__ X, int nh, int total)
{
    int idx = blockIdx.x * blockDim.x + threadIdx.x;
    if (idx >= total) return;
    int d = idx & 63;
    int h = (idx >> 6) % nh;
    int s = idx / (64 * nh);
    float e    = (float)(2 * d) * (1.0f / 128.0f);
    float invf = 1.0f / powf(10000.0f, e);
    float ang  = (float)s * invf;
    float c = cosf(ang), sn = sinf(ang);
    float* p = X + (long)s * (nh * HD) + h * HD;
    float x1 = p[d], x2 = p[d + 64];
    p[d]      = x1 * c - x2 * sn;
    p[d + 64] = x2 * c + x1 * sn;
}

// ============================================================================
// Causal row softmax in place on g_S. grid (S, NH), 256 threads.
// Zero-fills k > q so downstream kernels can read the full row.
// ============================================================================
__global__ __launch_bounds__(256)
void softmax_causal(float* __restrict__ Sm)
{
    const int q = blockIdx.x, h = blockIdx.y;
    float* row = Sm + ((long)h * S_LEN + q) * S_LEN;
    const int len = q + 1;
    const int tid = threadIdx.x;
    __shared__ float red[256];

    float m = -INFINITY;
    for (int i = tid; i < len; i += 256) m = fmaxf(m, row[i]);
    red[tid] = m; __syncthreads();
    for (int s = 128; s > 0; s >>= 1) {
        if (tid < s) red[tid] = fmaxf(red[tid], red[tid + s]);
        __syncthreads();
    }
    m = red[0]; __syncthreads();

    float sum = 0.0f;
    for (int i = tid; i < len; i += 256) sum += expf(row[i] - m);
    red[tid] = sum; __syncthreads();
    for (int s = 128; s > 0; s >>= 1) {
        if (tid < s) red[tid] += red[tid + s];
        __syncthreads();
    }
    const float inv = 1.0f / red[0];

    for (int i = tid; i < len; i += 256) row[i] = expf(row[i] - m) * inv;
    for (int i = len + tid; i < S_LEN; i += 256) row[i] = 0.0f;
}

// ============================================================================
// Column sums: cs[h][k] = sum_q attn[h][q][k]. grid (S/256, NH).
// ============================================================================
__global__ __launch_bounds__(256)
void colsum_kernel(const float* __restrict__ attn, float* __restrict__ cs)
{
    const int k = blockIdx.x * 256 + threadIdx.x;
    const int h = blockIdx.y;
    const float* base = attn + (size_t)h * S_LEN * S_LEN;
    float s = 0.0f;
    for (int q = k; q < S_LEN; q++) s += base[(long)q * S_LEN + k];
    cs[h * S_LEN + k] = s;
}

// ============================================================================
// H2O mask: per head, top-HB of colsum[0:SEL] plus last RB columns.
// mask: [NH, S+1]. grid (NH), 256 threads.
// ============================================================================
__global__ __launch_bounds__(256)
void h2o_mask(const float* __restrict__ cs, float* __restrict__ mask)
{
    const int h = blockIdx.x;
    const int tid = threadIdx.x;
    __shared__ float vals[SEL];
    __shared__ float bval[256];
    __shared__ int   bidx[256];

    for (int i = tid; i < SEL; i += 256) vals[i] = cs[h * S_LEN + i];
    float* mrow = mask + h * (S_LEN + 1);
    for (int i = tid; i < S_LEN + 1; i += 256)
        mrow[i] = (i >= (S_LEN + 1 - RB)) ? 1.0f : 0.0f;
    __syncthreads();

    for (int it = 0; it < HB; it++) {
        float best = -INFINITY; int bi = SEL;
        for (int i = tid; i < SEL; i += 256) {
            float v = vals[i];
            if (v > best) { best = v; bi = i; }
        }
        bval[tid] = best; bidx[tid] = bi; __syncthreads();
        for (int s = 128; s > 0; s >>= 1) {
            if (tid < s) {
                if (bval[tid + s] > bval[tid] ||
                    (bval[tid + s] == bval[tid] && bidx[tid + s] < bidx[tid])) {
                    bval[tid] = bval[tid + s];
                    bidx[tid] = bidx[tid + s];
                }
            }
            __syncthreads();
        }
        if (tid == 0) {
            mrow[bidx[0]] = 1.0f;
            vals[bidx[0]] = -INFINITY;
        }
        __syncthreads();
    }
}

// ============================================================================
// Host launcher
// ============================================================================
extern "C" void kernel_launch(void* const* d_in, const int* in_sizes, int n_in,
                              void* d_out, int out_size)
{
    const float* H  = (const float*)d_in[0];
    const float* Wq = (const float*)d_in[1];
    const float* Wk = (const float*)d_in[2];
    const float* Wv = (const float*)d_in[3];
    const float* Wo = (const float*)d_in[4];
    float* out = (float*)d_out;

    float *Q, *K, *V, *Sm, *O, *CS;
    cudaGetSymbolAddress((void**)&Q,  g_Q);
    cudaGetSymbolAddress((void**)&K,  g_K);
    cudaGetSymbolAddress((void**)&V,  g_V);
    cudaGetSymbolAddress((void**)&Sm, g_S);
    cudaGetSymbolAddress((void**)&O,  g_O);
    cudaGetSymbolAddress((void**)&CS, g_CS);

    const float inv_sqrt_hd = 0.08838834764831845f; // 1/sqrt(128)

    // 1-3. QKV projections (C = H * W^T)
    gemm_abt<<<dim3(HID / 128, S_LEN / 128, 1), 256>>>(
        H, Wq, Q, HID, HID, HID, HID, 0, 0, 0, 0, 1.0f, 0);
    gemm_abt<<<dim3((NKV * HD) / 128, S_LEN / 128, 1), 256>>>(
        H, Wk, K, HID, HID, HID, NKV * HD, 0, 0, 0, 0, 1.0f, 0);
    gemm_abt<<<dim3((NKV * HD) / 128, S_LEN / 128, 1), 256>>>(
        H, Wv, V, HID, HID, HID, NKV * HD, 0, 0, 0, 0, 1.0f, 0);

    // 4-5. RoPE
    {
        int totQ = S_LEN * NH * 64;
        rope_kernel<<<(totQ + 255) / 256, 256>>>(Q, NH, totQ);
        int totK = S_LEN * NKV * 64;
        rope_kernel<<<(totK + 255) / 256, 256>>>(K, NKV, totK);
    }

    // 6. scores = Q K^T / sqrt(HD), causal lower-triangle blocks only
    gemm_abt<<<dim3(S_LEN / 128, S_LEN / 128, NH), 256>>>(
        Q, K, Sm, HD, HID, NKV * HD, S_LEN,
        /*aHS*/ HD, /*bHS*/ HD, /*cHS*/ (long)S_LEN * S_LEN,
        /*bShift*/ 2, inv_sqrt_hd, /*causal*/ 1);

    // 7. row softmax (zero-fills upper triangle)
    softmax_causal<<<dim3(S_LEN, NH), 256>>>(Sm);

    // 8. column sums for H2O
    colsum_kernel<<<dim3(S_LEN / 256, NH), 256>>>(Sm, CS);

    // 9. context = attn * V (K-limited by causality), written per-head into O
    gemm_ab<<<dim3(HD / 128, S_LEN / 128, NH), 256>>>(
        Sm, V, O, S_LEN, S_LEN, NKV * HD, HID,
        /*aHS*/ (long)S_LEN * S_LEN, /*bHS*/ HD, /*cHS*/ HD,
        /*bShift*/ 2, 1.0f, /*causal*/ 1);

    // 10. attn_output = O * Wo^T -> d_out
    gemm_abt<<<dim3(HID / 128, S_LEN / 128, 1), 256>>>(
        O, Wo, out, HID, HID, HID, HID, 0, 0, 0, 0, 1.0f, 0);

    // 11. H2O mask -> tail of d_out
    {
        size_t maskOff = (size_t)out_size - (size_t)NH * (S_LEN + 1);
        h2o_mask<<<NH, 256>>>(CS, out + maskOff);
    }
}

// round 5
// speedup vs baseline: 1.1294x; 1.1294x over previous
#include <cuda_runtime.h>
#include <cuda_bf16.h>
#include <math.h>
#include <stdint.h>

// ----------------------------------------------------------------------------
// LlamaAttention + H2O mask. Staged 3xTF32 tensor-core GEMMs:
// operands split big/small (tf32); per k=8 step the 3-MMA triple accumulates
// into a zeroed temp (D = A*B + 0), which is folded into a persistent fp32
// accumulator with RN FADDs. Breaks the tensor-core truncating-accumulate
// chain that produced the 1.4e-4 error floor in round 4.
// B=1, S=2048, HID=4096, NH=32, NKV=8, HD=128, GROUPS=4, HB=RB=204
// ----------------------------------------------------------------------------

#define S_LEN   2048
#define HID     4096
#define NH      32
#define NKV     8
#define HD      128
#define HB      204
#define RB      204
#define SEL     (S_LEN - RB)   // 1844

__device__ float g_Q [S_LEN * HID];
__device__ float g_K [S_LEN * NKV * HD];
__device__ float g_V [S_LEN * NKV * HD];
__device__ float g_S [(size_t)NH * S_LEN * S_LEN];
__device__ float g_O [S_LEN * HID];
__device__ float g_CS[NH * S_LEN];

// fp32 -> tf32 bit pattern in b32 register
__device__ __forceinline__ uint32_t to_tf32(float x) {
    uint32_t y;
    asm("cvt.rna.tf32.f32 %0, %1;" : "=r"(y) : "f"(x));
    return y;
}

// split x into big (tf32) and small (tf32 of residual)
__device__ __forceinline__ void split_tf32(float x, uint32_t& b, uint32_t& s) {
    b = to_tf32(x);
    s = to_tf32(x - __uint_as_float(b));
}

// D += A*B (chained accumulate, used only within a 3-term triple)
__device__ __forceinline__ void mma_tf32(float* c, const uint32_t* a, const uint32_t* b) {
    asm volatile(
        "mma.sync.aligned.m16n8k8.row.col.f32.tf32.tf32.f32 "
        "{%0,%1,%2,%3}, {%4,%5,%6,%7}, {%8,%9}, {%0,%1,%2,%3};"
        : "+f"(c[0]), "+f"(c[1]), "+f"(c[2]), "+f"(c[3])
        : "r"(a[0]), "r"(a[1]), "r"(a[2]), "r"(a[3]), "r"(b[0]), "r"(b[1]));
}

// D = A*B + 0 (starts a fresh accumulation chain, no zero-init FADDs needed)
__device__ __forceinline__ void mma_tf32_zero(float* d, const uint32_t* a, const uint32_t* b) {
    asm volatile(
        "mma.sync.aligned.m16n8k8.row.col.f32.tf32.tf32.f32 "
        "{%0,%1,%2,%3}, {%4,%5,%6,%7}, {%8,%9}, {%10,%11,%12,%13};"
        : "=f"(d[0]), "=f"(d[1]), "=f"(d[2]), "=f"(d[3])
        : "r"(a[0]), "r"(a[1]), "r"(a[2]), "r"(a[3]), "r"(b[0]), "r"(b[1]),
          "f"(0.0f), "f"(0.0f), "f"(0.0f), "f"(0.0f));
}

// staged 3-term triple: acc += small_a*big_b + big_a*small_b + big_a*big_b
__device__ __forceinline__ void mma3_staged(float* acc,
                                            const uint32_t* aB, const uint32_t* aS,
                                            const uint32_t* bB, const uint32_t* bS) {
    float tmp[4];
    mma_tf32_zero(tmp, aS, bB);
    mma_tf32(tmp, aB, bS);
    mma_tf32(tmp, aB, bB);
    acc[0] += tmp[0];
    acc[1] += tmp[1];
    acc[2] += tmp[2];
    acc[3] += tmp[3];
}

// ============================================================================
// Staged 3xTF32 GEMM: C = alpha * A * B^T
// A: M x K row-major (lda), B: N x K row-major (ldb), C: M x N row-major (ldc)
// grid (N/128, M/128, heads). causal=1: skip blocks bx > by.
// ============================================================================
__global__ __launch_bounds__(256)
void gemm_abt(const float* __restrict__ A, const float* __restrict__ B,
              float* __restrict__ C,
              int K, int lda, int ldb, int ldc,
              long aHS, long bHS, long cHS, int bShift,
              float alpha, int causal)
{
    const int h = blockIdx.z;
    A += (long)h * aHS;
    B += (long)(h >> bShift) * bHS;
    C += (long)h * cHS;
    const int bx = blockIdx.x, by = blockIdx.y;
    if (causal && bx > by) return;

    __shared__ uint32_t AsB[16][132];
    __shared__ uint32_t AsS[16][132];
    __shared__ uint32_t BsB[16][132];
    __shared__ uint32_t BsS[16][132];

    const int tid  = threadIdx.x;
    const int lane = tid & 31;
    const int wid  = tid >> 5;
    const int g    = lane >> 2;
    const int tig  = lane & 3;
    const int mbase = (wid >> 2) * 64;
    const int nbase = (wid & 3) * 32;

    const int lrow = tid >> 2;           // 0..63 (+64)
    const int lcol = (tid & 3) * 4;

    const float* Ab = A + (long)(by * 128) * lda;
    const float* Bb = B + (long)(bx * 128) * ldb;

    float acc[4][4][4];
#pragma unroll
    for (int i = 0; i < 4; i++)
#pragma unroll
        for (int j = 0; j < 4; j++)
#pragma unroll
            for (int k = 0; k < 4; k++) acc[i][j][k] = 0.0f;

    float4 ra[2], rb[2];
#pragma unroll
    for (int r = 0; r < 2; r++) {
        ra[r] = *(const float4*)(Ab + (long)(lrow + r * 64) * lda + lcol);
        rb[r] = *(const float4*)(Bb + (long)(lrow + r * 64) * ldb + lcol);
    }

    for (int kk = 0; kk < K; kk += 16) {
#pragma unroll
        for (int r = 0; r < 2; r++) {
            const int row = lrow + r * 64;
            split_tf32(ra[r].x, AsB[lcol + 0][row], AsS[lcol + 0][row]);
            split_tf32(ra[r].y, AsB[lcol + 1][row], AsS[lcol + 1][row]);
            split_tf32(ra[r].z, AsB[lcol + 2][row], AsS[lcol + 2][row]);
            split_tf32(ra[r].w, AsB[lcol + 3][row], AsS[lcol + 3][row]);
            split_tf32(rb[r].x, BsB[lcol + 0][row], BsS[lcol + 0][row]);
            split_tf32(rb[r].y, BsB[lcol + 1][row], BsS[lcol + 1][row]);
            split_tf32(rb[r].z, BsB[lcol + 2][row], BsS[lcol + 2][row]);
            split_tf32(rb[r].w, BsB[lcol + 3][row], BsS[lcol + 3][row]);
        }
        __syncthreads();

        if (kk + 16 < K) {
#pragma unroll
            for (int r = 0; r < 2; r++) {
                ra[r] = *(const float4*)(Ab + (long)(lrow + r * 64) * lda + kk + 16 + lcol);
                rb[r] = *(const float4*)(Bb + (long)(lrow + r * 64) * ldb + kk + 16 + lcol);
            }
        }

#pragma unroll
        for (int ks = 0; ks < 16; ks += 8) {
            uint32_t afB[4][4], afS[4][4], bfB[4][2], bfS[4][2];
#pragma unroll
            for (int mt = 0; mt < 4; mt++) {
                const int r0 = mbase + mt * 16 + g;
                afB[mt][0] = AsB[ks + tig    ][r0    ];
                afB[mt][1] = AsB[ks + tig    ][r0 + 8];
                afB[mt][2] = AsB[ks + tig + 4][r0    ];
                afB[mt][3] = AsB[ks + tig + 4][r0 + 8];
                afS[mt][0] = AsS[ks + tig    ][r0    ];
                afS[mt][1] = AsS[ks + tig    ][r0 + 8];
                afS[mt][2] = AsS[ks + tig + 4][r0    ];
                afS[mt][3] = AsS[ks + tig + 4][r0 + 8];
            }
#pragma unroll
            for (int nt = 0; nt < 4; nt++) {
                const int c0 = nbase + nt * 8 + g;
                bfB[nt][0] = BsB[ks + tig    ][c0];
                bfB[nt][1] = BsB[ks + tig + 4][c0];
                bfS[nt][0] = BsS[ks + tig    ][c0];
                bfS[nt][1] = BsS[ks + tig + 4][c0];
            }
#pragma unroll
            for (int mt = 0; mt < 4; mt++)
#pragma unroll
                for (int nt = 0; nt < 4; nt++)
                    mma3_staged(acc[mt][nt], afB[mt], afS[mt], bfB[nt], bfS[nt]);
        }
        __syncthreads();
    }

#pragma unroll
    for (int mt = 0; mt < 4; mt++) {
#pragma unroll
        for (int nt = 0; nt < 4; nt++) {
            const int row0 = by * 128 + mbase + mt * 16 + g;
            const int col0 = bx * 128 + nbase + nt * 8 + 2 * tig;
            C[(long)row0 * ldc + col0    ] = alpha * acc[mt][nt][0];
            C[(long)row0 * ldc + col0 + 1] = alpha * acc[mt][nt][1];
            C[(long)(row0 + 8) * ldc + col0    ] = alpha * acc[mt][nt][2];
            C[(long)(row0 + 8) * ldc + col0 + 1] = alpha * acc[mt][nt][3];
        }
    }
}

// ============================================================================
// Staged 3xTF32 GEMM: C = alpha * A * B   (B row-major K x N)
// causal=1: limit K to (by+1)*128 (A block-lower-triangular).
// ============================================================================
__global__ __launch_bounds__(256)
void gemm_ab(const float* __restrict__ A, const float* __restrict__ B,
             float* __restrict__ C,
             int K, int lda, int ldb, int ldc,
             long aHS, long bHS, long cHS, int bShift,
             float alpha, int causal)
{
    const int h = blockIdx.z;
    A += (long)h * aHS;
    B += (long)(h >> bShift) * bHS;
    C += (long)h * cHS;
    const int bx = blockIdx.x, by = blockIdx.y;

    __shared__ uint32_t AsB[16][132];
    __shared__ uint32_t AsS[16][132];
    __shared__ uint32_t BsB[16][132];
    __shared__ uint32_t BsS[16][132];

    const int tid  = threadIdx.x;
    const int lane = tid & 31;
    const int wid  = tid >> 5;
    const int g    = lane >> 2;
    const int tig  = lane & 3;
    const int mbase = (wid >> 2) * 64;
    const int nbase = (wid & 3) * 32;

    const int lrow  = tid >> 2;
    const int lcol  = (tid & 3) * 4;
    const int brow  = tid >> 5;          // 0..7 (+8)
    const int bcol4 = (tid & 31) * 4;

    const float* Ab = A + (long)(by * 128) * lda;

    const int Keff = causal ? (((by + 1) * 128 < K) ? (by + 1) * 128 : K) : K;

    float acc[4][4][4];
#pragma unroll
    for (int i = 0; i < 4; i++)
#pragma unroll
        for (int j = 0; j < 4; j++)
#pragma unroll
            for (int k = 0; k < 4; k++) acc[i][j][k] = 0.0f;

    float4 ra[2], rb[2];
#pragma unroll
    for (int r = 0; r < 2; r++) {
        ra[r] = *(const float4*)(Ab + (long)(lrow + r * 64) * lda + lcol);
        rb[r] = *(const float4*)(B + (long)(brow + r * 8) * ldb + bx * 128 + bcol4);
    }

    for (int kk = 0; kk < Keff; kk += 16) {
#pragma unroll
        for (int r = 0; r < 2; r++) {
            const int row = lrow + r * 64;
            split_tf32(ra[r].x, AsB[lcol + 0][row], AsS[lcol + 0][row]);
            split_tf32(ra[r].y, AsB[lcol + 1][row], AsS[lcol + 1][row]);
            split_tf32(ra[r].z, AsB[lcol + 2][row], AsS[lcol + 2][row]);
            split_tf32(ra[r].w, AsB[lcol + 3][row], AsS[lcol + 3][row]);
            const int krow = brow + r * 8;
            split_tf32(rb[r].x, BsB[krow][bcol4 + 0], BsS[krow][bcol4 + 0]);
            split_tf32(rb[r].y, BsB[krow][bcol4 + 1], BsS[krow][bcol4 + 1]);
            split_tf32(rb[r].z, BsB[krow][bcol4 + 2], BsS[krow][bcol4 + 2]);
            split_tf32(rb[r].w, BsB[krow][bcol4 + 3], BsS[krow][bcol4 + 3]);
        }
        __syncthreads();

        if (kk + 16 < Keff) {
#pragma unroll
            for (int r = 0; r < 2; r++) {
                ra[r] = *(const float4*)(Ab + (long)(lrow + r * 64) * lda + kk + 16 + lcol);
                rb[r] = *(const float4*)(B + (long)(kk + 16 + brow + r * 8) * ldb + bx * 128 + bcol4);
            }
        }

#pragma unroll
        for (int ks = 0; ks < 16; ks += 8) {
            uint32_t afB[4][4], afS[4][4], bfB[4][2], bfS[4][2];
#pragma unroll
            for (int mt = 0; mt < 4; mt++) {
                const int r0 = mbase + mt * 16 + g;
                afB[mt][0] = AsB[ks + tig    ][r0    ];
                afB[mt][1] = AsB[ks + tig    ][r0 + 8];
                afB[mt][2] = AsB[ks + tig + 4][r0    ];
                afB[mt][3] = AsB[ks + tig + 4][r0 + 8];
                afS[mt][0] = AsS[ks + tig    ][r0    ];
                afS[mt][1] = AsS[ks + tig    ][r0 + 8];
                afS[mt][2] = AsS[ks + tig + 4][r0    ];
                afS[mt][3] = AsS[ks + tig + 4][r0 + 8];
            }
#pragma unroll
            for (int nt = 0; nt < 4; nt++) {
                const int c0 = nbase + nt * 8 + g;
                bfB[nt][0] = BsB[ks + tig    ][c0];
                bfB[nt][1] = BsB[ks + tig + 4][c0];
                bfS[nt][0] = BsS[ks + tig    ][c0];
                bfS[nt][1] = BsS[ks + tig + 4][c0];
            }
#pragma unroll
            for (int mt = 0; mt < 4; mt++)
#pragma unroll
                for (int nt = 0; nt < 4; nt++)
                    mma3_staged(acc[mt][nt], afB[mt], afS[mt], bfB[nt], bfS[nt]);
        }
        __syncthreads();
    }

#pragma unroll
    for (int mt = 0; mt < 4; mt++) {
#pragma unroll
        for (int nt = 0; nt < 4; nt++) {
            const int row0 = by * 128 + mbase + mt * 16 + g;
            const int col0 = bx * 128 + nbase + nt * 8 + 2 * tig;
            C[(long)row0 * ldc + col0    ] = alpha * acc[mt][nt][0];
            C[(long)row0 * ldc + col0 + 1] = alpha * acc[mt][nt][1];
            C[(long)(row0 + 8) * ldc + col0    ] = alpha * acc[mt][nt][2];
            C[(long)(row0 + 8) * ldc + col0 + 1] = alpha * acc[mt][nt][3];
        }
    }
}

// ============================================================================
// RoPE in place. X: [S, nh*HD]. One thread per (s, h, d<64).
// ============================================================================
__global__ void rope_kernel(float* __restrict__ X, int nh, int total)
{
    int idx = blockIdx.x * blockDim.x + threadIdx.x;
    if (idx >= total) return;
    int d = idx & 63;
    int h = (idx >> 6) % nh;
    int s = idx / (64 * nh);
    float e    = (float)(2 * d) * (1.0f / 128.0f);
    float invf = 1.0f / powf(10000.0f, e);
    float ang  = (float)s * invf;
    float c = cosf(ang), sn = sinf(ang);
    float* p = X + (long)s * (nh * HD) + h * HD;
    float x1 = p[d], x2 = p[d + 64];
    p[d]      = x1 * c - x2 * sn;
    p[d + 64] = x2 * c + x1 * sn;
}

// ============================================================================
// Causal row softmax in place on g_S; zero-fills upper triangle.
// ============================================================================
__global__ __launch_bounds__(256)
void softmax_causal(float* __restrict__ Sm)
{
    const int q = blockIdx.x, h = blockIdx.y;
    float* row = Sm + ((long)h * S_LEN + q) * S_LEN;
    const int len = q + 1;
    const int tid = threadIdx.x;
    __shared__ float red[256];

    float m = -INFINITY;
    for (int i = tid; i < len; i += 256) m = fmaxf(m, row[i]);
    red[tid] = m; __syncthreads();
    for (int s = 128; s > 0; s >>= 1) {
        if (tid < s) red[tid] = fmaxf(red[tid], red[tid + s]);
        __syncthreads();
    }
    m = red[0]; __syncthreads();

    float sum = 0.0f;
    for (int i = tid; i < len; i += 256) sum += expf(row[i] - m);
    red[tid] = sum; __syncthreads();
    for (int s = 128; s > 0; s >>= 1) {
        if (tid < s) red[tid] += red[tid + s];
        __syncthreads();
    }
    const float inv = 1.0f / red[0];

    for (int i = tid; i < len; i += 256) row[i] = expf(row[i] - m) * inv;
    for (int i = len + tid; i < S_LEN; i += 256) row[i] = 0.0f;
}

// ============================================================================
// Column sums: cs[h][k] = sum_q attn[h][q][k].
// ============================================================================
__global__ __launch_bounds__(256)
void colsum_kernel(const float* __restrict__ attn, float* __restrict__ cs)
{
    const int k = blockIdx.x * 256 + threadIdx.x;
    const int h = blockIdx.y;
    const float* base = attn + (size_t)h * S_LEN * S_LEN;
    float s = 0.0f;
    for (int q = k; q < S_LEN; q++) s += base[(long)q * S_LEN + k];
    cs[h * S_LEN + k] = s;
}

// ============================================================================
// H2O mask: per head top-HB of colsum[0:SEL] + last RB columns.
// ============================================================================
__global__ __launch_bounds__(256)
void h2o_mask(const float* __restrict__ cs, float* __restrict__ mask)
{
    const int h = blockIdx.x;
    const int tid = threadIdx.x;
    __shared__ float vals[SEL];
    __shared__ float bval[256];
    __shared__ int   bidx[256];

    for (int i = tid; i < SEL; i += 256) vals[i] = cs[h * S_LEN + i];
    float* mrow = mask + h * (S_LEN + 1);
    for (int i = tid; i < S_LEN + 1; i += 256)
        mrow[i] = (i >= (S_LEN + 1 - RB)) ? 1.0f : 0.0f;
    __syncthreads();

    for (int it = 0; it < HB; it++) {
        float best = -INFINITY; int bi = SEL;
        for (int i = tid; i < SEL; i += 256) {
            float v = vals[i];
            if (v > best) { best = v; bi = i; }
        }
        bval[tid] = best; bidx[tid] = bi; __syncthreads();
        for (int s = 128; s > 0; s >>= 1) {
            if (tid < s) {
                if (bval[tid + s] > bval[tid] ||
                    (bval[tid + s] == bval[tid] && bidx[tid + s] < bidx[tid])) {
                    bval[tid] = bval[tid + s];
                    bidx[tid] = bidx[tid + s];
                }
            }
            __syncthreads();
        }
        if (tid == 0) {
            mrow[bidx[0]] = 1.0f;
            vals[bidx[0]] = -INFINITY;
        }
        __syncthreads();
    }
}

// ============================================================================
// Host launcher
// ============================================================================
extern "C" void kernel_launch(void* const* d_in, const int* in_sizes, int n_in,
                              void* d_out, int out_size)
{
    const float* H  = (const float*)d_in[0];
    const float* Wq = (const float*)d_in[1];
    const float* Wk = (const float*)d_in[2];
    const float* Wv = (const float*)d_in[3];
    const float* Wo = (const float*)d_in[4];
    float* out = (float*)d_out;

    float *Q, *K, *V, *Sm, *O, *CS;
    cudaGetSymbolAddress((void**)&Q,  g_Q);
    cudaGetSymbolAddress((void**)&K,  g_K);
    cudaGetSymbolAddress((void**)&V,  g_V);
    cudaGetSymbolAddress((void**)&Sm, g_S);
    cudaGetSymbolAddress((void**)&O,  g_O);
    cudaGetSymbolAddress((void**)&CS, g_CS);

    const float inv_sqrt_hd = 0.08838834764831845f; // 1/sqrt(128)

    // QKV projections (C = H * W^T)
    gemm_abt<<<dim3(HID / 128, S_LEN / 128, 1), 256>>>(
        H, Wq, Q, HID, HID, HID, HID, 0, 0, 0, 0, 1.0f, 0);
    gemm_abt<<<dim3((NKV * HD) / 128, S_LEN / 128, 1), 256>>>(
        H, Wk, K, HID, HID, HID, NKV * HD, 0, 0, 0, 0, 1.0f, 0);
    gemm_abt<<<dim3((NKV * HD) / 128, S_LEN / 128, 1), 256>>>(
        H, Wv, V, HID, HID, HID, NKV * HD, 0, 0, 0, 0, 1.0f, 0);

    // RoPE
    {
        int totQ = S_LEN * NH * 64;
        rope_kernel<<<(totQ + 255) / 256, 256>>>(Q, NH, totQ);
        int totK = S_LEN * NKV * 64;
        rope_kernel<<<(totK + 255) / 256, 256>>>(K, NKV, totK);
    }

    // scores = Q K^T / sqrt(HD), lower-triangle blocks only
    gemm_abt<<<dim3(S_LEN / 128, S_LEN / 128, NH), 256>>>(
        Q, K, Sm, HD, HID, NKV * HD, S_LEN,
        HD, HD, (long)S_LEN * S_LEN, 2, inv_sqrt_hd, 1);

    // softmax (zero-fills upper triangle)
    softmax_causal<<<dim3(S_LEN, NH), 256>>>(Sm);

    // column sums
    colsum_kernel<<<dim3(S_LEN / 256, NH), 256>>>(Sm, CS);

    // context = attn * V
    gemm_ab<<<dim3(HD / 128, S_LEN / 128, NH), 256>>>(
        Sm, V, O, S_LEN, S_LEN, NKV * HD, HID,
        (long)S_LEN * S_LEN, HD, HD, 2, 1.0f, 1);

    // attn_output = O * Wo^T
    gemm_abt<<<dim3(HID / 128, S_LEN / 128, 1), 256>>>(
        O, Wo, out, HID, HID, HID, HID, 0, 0, 0, 0, 1.0f, 0);

    // H2O mask
    {
        size_t maskOff = (size_t)out_size - (size_t)NH * (S_LEN + 1);
        h2o_mask<<<NH, 256>>>(CS, out + maskOff);
    }
}

// round 6
// speedup vs baseline: 1.4163x; 1.2541x over previous
#include <cuda_runtime.h>
#include <cuda_bf16.h>
#include <math.h>
#include <stdint.h>

// ----------------------------------------------------------------------------
// LlamaAttention + H2O mask. Hybrid-precision tensor-core GEMMs:
//   - staged 3xTF32 (fp32-grade) for Wq, Wk, Wv projections and QK^T scores
//     (the path feeding softmax/colsum/top-k mask -> mask stays exact)
//   - plain 1xTF32 for attn*V and the Wo output projection (only Output 0,
//     ~5e-4 total error, under the 1e-3 gate; saves 205 GFLOP-equiv of MMA)
// B=1, S=2048, HID=4096, NH=32, NKV=8, HD=128, GROUPS=4, HB=RB=204
// ----------------------------------------------------------------------------

#define S_LEN   2048
#define HID     4096
#define NH      32
#define NKV     8
#define HD      128
#define HB      204
#define RB      204
#define SEL     (S_LEN - RB)   // 1844

__device__ float g_Q [S_LEN * HID];
__device__ float g_K [S_LEN * NKV * HD];
__device__ float g_V [S_LEN * NKV * HD];
__device__ float g_S [(size_t)NH * S_LEN * S_LEN];
__device__ float g_O [S_LEN * HID];
__device__ float g_CS[NH * S_LEN];

// fp32 -> tf32 bit pattern in b32 register
__device__ __forceinline__ uint32_t to_tf32(float x) {
    uint32_t y;
    asm("cvt.rna.tf32.f32 %0, %1;" : "=r"(y) : "f"(x));
    return y;
}

// split x into big (tf32) and small (tf32 of residual)
__device__ __forceinline__ void split_tf32(float x, uint32_t& b, uint32_t& s) {
    b = to_tf32(x);
    s = to_tf32(x - __uint_as_float(b));
}

// D += A*B (chained accumulate)
__device__ __forceinline__ void mma_tf32(float* c, const uint32_t* a, const uint32_t* b) {
    asm volatile(
        "mma.sync.aligned.m16n8k8.row.col.f32.tf32.tf32.f32 "
        "{%0,%1,%2,%3}, {%4,%5,%6,%7}, {%8,%9}, {%0,%1,%2,%3};"
        : "+f"(c[0]), "+f"(c[1]), "+f"(c[2]), "+f"(c[3])
        : "r"(a[0]), "r"(a[1]), "r"(a[2]), "r"(a[3]), "r"(b[0]), "r"(b[1]));
}

// D = A*B + 0 (starts a fresh accumulation chain)
__device__ __forceinline__ void mma_tf32_zero(float* d, const uint32_t* a, const uint32_t* b) {
    asm volatile(
        "mma.sync.aligned.m16n8k8.row.col.f32.tf32.tf32.f32 "
        "{%0,%1,%2,%3}, {%4,%5,%6,%7}, {%8,%9}, {%10,%11,%12,%13};"
        : "=f"(d[0]), "=f"(d[1]), "=f"(d[2]), "=f"(d[3])
        : "r"(a[0]), "r"(a[1]), "r"(a[2]), "r"(a[3]), "r"(b[0]), "r"(b[1]),
          "f"(0.0f), "f"(0.0f), "f"(0.0f), "f"(0.0f));
}

// staged 3-term triple: acc += small_a*big_b + big_a*small_b + big_a*big_b
__device__ __forceinline__ void mma3_staged(float* acc,
                                            const uint32_t* aB, const uint32_t* aS,
                                            const uint32_t* bB, const uint32_t* bS) {
    float tmp[4];
    mma_tf32_zero(tmp, aS, bB);
    mma_tf32(tmp, aB, bS);
    mma_tf32(tmp, aB, bB);
    acc[0] += tmp[0];
    acc[1] += tmp[1];
    acc[2] += tmp[2];
    acc[3] += tmp[3];
}

// ============================================================================
// Staged 3xTF32 GEMM: C = alpha * A * B^T   (accurate path)
// A: M x K row-major (lda), B: N x K row-major (ldb), C: M x N row-major (ldc)
// grid (N/128, M/128, heads). causal=1: skip blocks bx > by.
// ============================================================================
__global__ __launch_bounds__(256)
void gemm_abt3(const float* __restrict__ A, const float* __restrict__ B,
               float* __restrict__ C,
               int K, int lda, int ldb, int ldc,
               long aHS, long bHS, long cHS, int bShift,
               float alpha, int causal)
{
    const int h = blockIdx.z;
    A += (long)h * aHS;
    B += (long)(h >> bShift) * bHS;
    C += (long)h * cHS;
    const int bx = blockIdx.x, by = blockIdx.y;
    if (causal && bx > by) return;

    __shared__ uint32_t AsB[16][132];
    __shared__ uint32_t AsS[16][132];
    __shared__ uint32_t BsB[16][132];
    __shared__ uint32_t BsS[16][132];

    const int tid  = threadIdx.x;
    const int lane = tid & 31;
    const int wid  = tid >> 5;
    const int g    = lane >> 2;
    const int tig  = lane & 3;
    const int mbase = (wid >> 2) * 64;
    const int nbase = (wid & 3) * 32;

    const int lrow = tid >> 2;           // 0..63 (+64)
    const int lcol = (tid & 3) * 4;

    const float* Ab = A + (long)(by * 128) * lda;
    const float* Bb = B + (long)(bx * 128) * ldb;

    float acc[4][4][4];
#pragma unroll
    for (int i = 0; i < 4; i++)
#pragma unroll
        for (int j = 0; j < 4; j++)
#pragma unroll
            for (int k = 0; k < 4; k++) acc[i][j][k] = 0.0f;

    float4 ra[2], rb[2];
#pragma unroll
    for (int r = 0; r < 2; r++) {
        ra[r] = *(const float4*)(Ab + (long)(lrow + r * 64) * lda + lcol);
        rb[r] = *(const float4*)(Bb + (long)(lrow + r * 64) * ldb + lcol);
    }

    for (int kk = 0; kk < K; kk += 16) {
#pragma unroll
        for (int r = 0; r < 2; r++) {
            const int row = lrow + r * 64;
            split_tf32(ra[r].x, AsB[lcol + 0][row], AsS[lcol + 0][row]);
            split_tf32(ra[r].y, AsB[lcol + 1][row], AsS[lcol + 1][row]);
            split_tf32(ra[r].z, AsB[lcol + 2][row], AsS[lcol + 2][row]);
            split_tf32(ra[r].w, AsB[lcol + 3][row], AsS[lcol + 3][row]);
            split_tf32(rb[r].x, BsB[lcol + 0][row], BsS[lcol + 0][row]);
            split_tf32(rb[r].y, BsB[lcol + 1][row], BsS[lcol + 1][row]);
            split_tf32(rb[r].z, BsB[lcol + 2][row], BsS[lcol + 2][row]);
            split_tf32(rb[r].w, BsB[lcol + 3][row], BsS[lcol + 3][row]);
        }
        __syncthreads();

        if (kk + 16 < K) {
#pragma unroll
            for (int r = 0; r < 2; r++) {
                ra[r] = *(const float4*)(Ab + (long)(lrow + r * 64) * lda + kk + 16 + lcol);
                rb[r] = *(const float4*)(Bb + (long)(lrow + r * 64) * ldb + kk + 16 + lcol);
            }
        }

#pragma unroll
        for (int ks = 0; ks < 16; ks += 8) {
            uint32_t afB[4][4], afS[4][4], bfB[4][2], bfS[4][2];
#pragma unroll
            for (int mt = 0; mt < 4; mt++) {
                const int r0 = mbase + mt * 16 + g;
                afB[mt][0] = AsB[ks + tig    ][r0    ];
                afB[mt][1] = AsB[ks + tig    ][r0 + 8];
                afB[mt][2] = AsB[ks + tig + 4][r0    ];
                afB[mt][3] = AsB[ks + tig + 4][r0 + 8];
                afS[mt][0] = AsS[ks + tig    ][r0    ];
                afS[mt][1] = AsS[ks + tig    ][r0 + 8];
                afS[mt][2] = AsS[ks + tig + 4][r0    ];
                afS[mt][3] = AsS[ks + tig + 4][r0 + 8];
            }
#pragma unroll
            for (int nt = 0; nt < 4; nt++) {
                const int c0 = nbase + nt * 8 + g;
                bfB[nt][0] = BsB[ks + tig    ][c0];
                bfB[nt][1] = BsB[ks + tig + 4][c0];
                bfS[nt][0] = BsS[ks + tig    ][c0];
                bfS[nt][1] = BsS[ks + tig + 4][c0];
            }
#pragma unroll
            for (int mt = 0; mt < 4; mt++)
#pragma unroll
                for (int nt = 0; nt < 4; nt++)
                    mma3_staged(acc[mt][nt], afB[mt], afS[mt], bfB[nt], bfS[nt]);
        }
        __syncthreads();
    }

#pragma unroll
    for (int mt = 0; mt < 4; mt++) {
#pragma unroll
        for (int nt = 0; nt < 4; nt++) {
            const int row0 = by * 128 + mbase + mt * 16 + g;
            const int col0 = bx * 128 + nbase + nt * 8 + 2 * tig;
            C[(long)row0 * ldc + col0    ] = alpha * acc[mt][nt][0];
            C[(long)row0 * ldc + col0 + 1] = alpha * acc[mt][nt][1];
            C[(long)(row0 + 8) * ldc + col0    ] = alpha * acc[mt][nt][2];
            C[(long)(row0 + 8) * ldc + col0 + 1] = alpha * acc[mt][nt][3];
        }
    }
}

// ============================================================================
// 1xTF32 GEMM: C = alpha * A * B^T   (fast path: Wo projection)
// ============================================================================
__global__ __launch_bounds__(256)
void gemm_abt1(const float* __restrict__ A, const float* __restrict__ B,
               float* __restrict__ C,
               int K, int lda, int ldb, int ldc, float alpha)
{
    const int bx = blockIdx.x, by = blockIdx.y;

    __shared__ uint32_t As[16][132];
    __shared__ uint32_t Bs[16][132];

    const int tid  = threadIdx.x;
    const int lane = tid & 31;
    const int wid  = tid >> 5;
    const int g    = lane >> 2;
    const int tig  = lane & 3;
    const int mbase = (wid >> 2) * 64;
    const int nbase = (wid & 3) * 32;

    const int lrow = tid >> 2;
    const int lcol = (tid & 3) * 4;

    const float* Ab = A + (long)(by * 128) * lda;
    const float* Bb = B + (long)(bx * 128) * ldb;

    float acc[4][4][4];
#pragma unroll
    for (int i = 0; i < 4; i++)
#pragma unroll
        for (int j = 0; j < 4; j++)
#pragma unroll
            for (int k = 0; k < 4; k++) acc[i][j][k] = 0.0f;

    float4 ra[2], rb[2];
#pragma unroll
    for (int r = 0; r < 2; r++) {
        ra[r] = *(const float4*)(Ab + (long)(lrow + r * 64) * lda + lcol);
        rb[r] = *(const float4*)(Bb + (long)(lrow + r * 64) * ldb + lcol);
    }

    for (int kk = 0; kk < K; kk += 16) {
#pragma unroll
        for (int r = 0; r < 2; r++) {
            const int row = lrow + r * 64;
            As[lcol + 0][row] = to_tf32(ra[r].x);
            As[lcol + 1][row] = to_tf32(ra[r].y);
            As[lcol + 2][row] = to_tf32(ra[r].z);
            As[lcol + 3][row] = to_tf32(ra[r].w);
            Bs[lcol + 0][row] = to_tf32(rb[r].x);
            Bs[lcol + 1][row] = to_tf32(rb[r].y);
            Bs[lcol + 2][row] = to_tf32(rb[r].z);
            Bs[lcol + 3][row] = to_tf32(rb[r].w);
        }
        __syncthreads();

        if (kk + 16 < K) {
#pragma unroll
            for (int r = 0; r < 2; r++) {
                ra[r] = *(const float4*)(Ab + (long)(lrow + r * 64) * lda + kk + 16 + lcol);
                rb[r] = *(const float4*)(Bb + (long)(lrow + r * 64) * ldb + kk + 16 + lcol);
            }
        }

#pragma unroll
        for (int ks = 0; ks < 16; ks += 8) {
            uint32_t af[4][4], bf[4][2];
#pragma unroll
            for (int mt = 0; mt < 4; mt++) {
                const int r0 = mbase + mt * 16 + g;
                af[mt][0] = As[ks + tig    ][r0    ];
                af[mt][1] = As[ks + tig    ][r0 + 8];
                af[mt][2] = As[ks + tig + 4][r0    ];
                af[mt][3] = As[ks + tig + 4][r0 + 8];
            }
#pragma unroll
            for (int nt = 0; nt < 4; nt++) {
                const int c0 = nbase + nt * 8 + g;
                bf[nt][0] = Bs[ks + tig    ][c0];
                bf[nt][1] = Bs[ks + tig + 4][c0];
            }
#pragma unroll
            for (int mt = 0; mt < 4; mt++)
#pragma unroll
                for (int nt = 0; nt < 4; nt++)
                    mma_tf32(acc[mt][nt], af[mt], bf[nt]);
        }
        __syncthreads();
    }

#pragma unroll
    for (int mt = 0; mt < 4; mt++) {
#pragma unroll
        for (int nt = 0; nt < 4; nt++) {
            const int row0 = by * 128 + mbase + mt * 16 + g;
            const int col0 = bx * 128 + nbase + nt * 8 + 2 * tig;
            C[(long)row0 * ldc + col0    ] = alpha * acc[mt][nt][0];
            C[(long)row0 * ldc + col0 + 1] = alpha * acc[mt][nt][1];
            C[(long)(row0 + 8) * ldc + col0    ] = alpha * acc[mt][nt][2];
            C[(long)(row0 + 8) * ldc + col0 + 1] = alpha * acc[mt][nt][3];
        }
    }
}

// ============================================================================
// 1xTF32 GEMM: C = alpha * A * B   (fast path: attn * V, per-head)
// causal=1: limit K to (by+1)*128 (A block-lower-triangular).
// ============================================================================
__global__ __launch_bounds__(256)
void gemm_ab1(const float* __restrict__ A, const float* __restrict__ B,
              float* __restrict__ C,
              int K, int lda, int ldb, int ldc,
              long aHS, long bHS, long cHS, int bShift,
              float alpha, int causal)
{
    const int h = blockIdx.z;
    A += (long)h * aHS;
    B += (long)(h >> bShift) * bHS;
    C += (long)h * cHS;
    const int bx = blockIdx.x, by = blockIdx.y;

    __shared__ uint32_t As[16][132];
    __shared__ uint32_t Bs[16][132];

    const int tid  = threadIdx.x;
    const int lane = tid & 31;
    const int wid  = tid >> 5;
    const int g    = lane >> 2;
    const int tig  = lane & 3;
    const int mbase = (wid >> 2) * 64;
    const int nbase = (wid & 3) * 32;

    const int lrow  = tid >> 2;
    const int lcol  = (tid & 3) * 4;
    const int brow  = tid >> 5;          // 0..7 (+8)
    const int bcol4 = (tid & 31) * 4;

    const float* Ab = A + (long)(by * 128) * lda;

    const int Keff = causal ? (((by + 1) * 128 < K) ? (by + 1) * 128 : K) : K;

    float acc[4][4][4];
#pragma unroll
    for (int i = 0; i < 4; i++)
#pragma unroll
        for (int j = 0; j < 4; j++)
#pragma unroll
            for (int k = 0; k < 4; k++) acc[i][j][k] = 0.0f;

    float4 ra[2], rb[2];
#pragma unroll
    for (int r = 0; r < 2; r++) {
        ra[r] = *(const float4*)(Ab + (long)(lrow + r * 64) * lda + lcol);
        rb[r] = *(const float4*)(B + (long)(brow + r * 8) * ldb + bx * 128 + bcol4);
    }

    for (int kk = 0; kk < Keff; kk += 16) {
#pragma unroll
        for (int r = 0; r < 2; r++) {
            const int row = lrow + r * 64;
            As[lcol + 0][row] = to_tf32(ra[r].x);
            As[lcol + 1][row] = to_tf32(ra[r].y);
            As[lcol + 2][row] = to_tf32(ra[r].z);
            As[lcol + 3][row] = to_tf32(ra[r].w);
            const int krow = brow + r * 8;
            Bs[krow][bcol4 + 0] = to_tf32(rb[r].x);
            Bs[krow][bcol4 + 1] = to_tf32(rb[r].y);
            Bs[krow][bcol4 + 2] = to_tf32(rb[r].z);
            Bs[krow][bcol4 + 3] = to_tf32(rb[r].w);
        }
        __syncthreads();

        if (kk + 16 < Keff) {
#pragma unroll
            for (int r = 0; r < 2; r++) {
                ra[r] = *(const float4*)(Ab + (long)(lrow + r * 64) * lda + kk + 16 + lcol);
                rb[r] = *(const float4*)(B + (long)(kk + 16 + brow + r * 8) * ldb + bx * 128 + bcol4);
            }
        }

#pragma unroll
        for (int ks = 0; ks < 16; ks += 8) {
            uint32_t af[4][4], bf[4][2];
#pragma unroll
            for (int mt = 0; mt < 4; mt++) {
                const int r0 = mbase + mt * 16 + g;
                af[mt][0] = As[ks + tig    ][r0    ];
                af[mt][1] = As[ks + tig    ][r0 + 8];
                af[mt][2] = As[ks + tig + 4][r0    ];
                af[mt][3] = As[ks + tig + 4][r0 + 8];
            }
#pragma unroll
            for (int nt = 0; nt < 4; nt++) {
                const int c0 = nbase + nt * 8 + g;
                bf[nt][0] = Bs[ks + tig    ][c0];
                bf[nt][1] = Bs[ks + tig + 4][c0];
            }
#pragma unroll
            for (int mt = 0; mt < 4; mt++)
#pragma unroll
                for (int nt = 0; nt < 4; nt++)
                    mma_tf32(acc[mt][nt], af[mt], bf[nt]);
        }
        __syncthreads();
    }

#pragma unroll
    for (int mt = 0; mt < 4; mt++) {
#pragma unroll
        for (int nt = 0; nt < 4; nt++) {
            const int row0 = by * 128 + mbase + mt * 16 + g;
            const int col0 = bx * 128 + nbase + nt * 8 + 2 * tig;
            C[(long)row0 * ldc + col0    ] = alpha * acc[mt][nt][0];
            C[(long)row0 * ldc + col0 + 1] = alpha * acc[mt][nt][1];
            C[(long)(row0 + 8) * ldc + col0    ] = alpha * acc[mt][nt][2];
            C[(long)(row0 + 8) * ldc + col0 + 1] = alpha * acc[mt][nt][3];
        }
    }
}

// ============================================================================
// RoPE in place. X: [S, nh*HD]. One thread per (s, h, d<64).
// ============================================================================
__global__ void rope_kernel(float* __restrict__ X, int nh, int total)
{
    int idx = blockIdx.x * blockDim.x + threadIdx.x;
    if (idx >= total) return;
    int d = idx & 63;
    int h = (idx >> 6) % nh;
    int s = idx / (64 * nh);
    float e    = (float)(2 * d) * (1.0f / 128.0f);
    float invf = 1.0f / powf(10000.0f, e);
    float ang  = (float)s * invf;
    float c = cosf(ang), sn = sinf(ang);
    float* p = X + (long)s * (nh * HD) + h * HD;
    float x1 = p[d], x2 = p[d + 64];
    p[d]      = x1 * c - x2 * sn;
    p[d + 64] = x2 * c + x1 * sn;
}

// ============================================================================
// Causal row softmax in place on g_S; zero-fills upper triangle.
// ============================================================================
__global__ __launch_bounds__(256)
void softmax_causal(float* __restrict__ Sm)
{
    const int q = blockIdx.x, h = blockIdx.y;
    float* row = Sm + ((long)h * S_LEN + q) * S_LEN;
    const int len = q + 1;
    const int tid = threadIdx.x;
    __shared__ float red[256];

    float m = -INFINITY;
    for (int i = tid; i < len; i += 256) m = fmaxf(m, row[i]);
    red[tid] = m; __syncthreads();
    for (int s = 128; s > 0; s >>= 1) {
        if (tid < s) red[tid] = fmaxf(red[tid], red[tid + s]);
        __syncthreads();
    }
    m = red[0]; __syncthreads();

    float sum = 0.0f;
    for (int i = tid; i < len; i += 256) sum += expf(row[i] - m);
    red[tid] = sum; __syncthreads();
    for (int s = 128; s > 0; s >>= 1) {
        if (tid < s) red[tid] += red[tid + s];
        __syncthreads();
    }
    const float inv = 1.0f / red[0];

    for (int i = tid; i < len; i += 256) row[i] = expf(row[i] - m) * inv;
    for (int i = len + tid; i < S_LEN; i += 256) row[i] = 0.0f;
}

// ============================================================================
// Column sums: cs[h][k] = sum_q attn[h][q][k].
// ============================================================================
__global__ __launch_bounds__(256)
void colsum_kernel(const float* __restrict__ attn, float* __restrict__ cs)
{
    const int k = blockIdx.x * 256 + threadIdx.x;
    const int h = blockIdx.y;
    const float* base = attn + (size_t)h * S_LEN * S_LEN;
    float s = 0.0f;
    for (int q = k; q < S_LEN; q++) s += base[(long)q * S_LEN + k];
    cs[h * S_LEN + k] = s;
}

// ============================================================================
// H2O mask: per head top-HB of colsum[0:SEL] + last RB columns.
// ============================================================================
__global__ __launch_bounds__(256)
void h2o_mask(const float* __restrict__ cs, float* __restrict__ mask)
{
    const int h = blockIdx.x;
    const int tid = threadIdx.x;
    __shared__ float vals[SEL];
    __shared__ float bval[256];
    __shared__ int   bidx[256];

    for (int i = tid; i < SEL; i += 256) vals[i] = cs[h * S_LEN + i];
    float* mrow = mask + h * (S_LEN + 1);
    for (int i = tid; i < S_LEN + 1; i += 256)
        mrow[i] = (i >= (S_LEN + 1 - RB)) ? 1.0f : 0.0f;
    __syncthreads();

    for (int it = 0; it < HB; it++) {
        float best = -INFINITY; int bi = SEL;
        for (int i = tid; i < SEL; i += 256) {
            float v = vals[i];
            if (v > best) { best = v; bi = i; }
        }
        bval[tid] = best; bidx[tid] = bi; __syncthreads();
        for (int s = 128; s > 0; s >>= 1) {
            if (tid < s) {
                if (bval[tid + s] > bval[tid] ||
                    (bval[tid + s] == bval[tid] && bidx[tid + s] < bidx[tid])) {
                    bval[tid] = bval[tid + s];
                    bidx[tid] = bidx[tid + s];
                }
            }
            __syncthreads();
        }
        if (tid == 0) {
            mrow[bidx[0]] = 1.0f;
            vals[bidx[0]] = -INFINITY;
        }
        __syncthreads();
    }
}

// ============================================================================
// Host launcher
// ============================================================================
extern "C" void kernel_launch(void* const* d_in, const int* in_sizes, int n_in,
                              void* d_out, int out_size)
{
    const float* H  = (const float*)d_in[0];
    const float* Wq = (const float*)d_in[1];
    const float* Wk = (const float*)d_in[2];
    const float* Wv = (const float*)d_in[3];
    const float* Wo = (const float*)d_in[4];
    float* out = (float*)d_out;

    float *Q, *K, *V, *Sm, *O, *CS;
    cudaGetSymbolAddress((void**)&Q,  g_Q);
    cudaGetSymbolAddress((void**)&K,  g_K);
    cudaGetSymbolAddress((void**)&V,  g_V);
    cudaGetSymbolAddress((void**)&Sm, g_S);
    cudaGetSymbolAddress((void**)&O,  g_O);
    cudaGetSymbolAddress((void**)&CS, g_CS);

    const float inv_sqrt_hd = 0.08838834764831845f; // 1/sqrt(128)

    // QKV projections (C = H * W^T): accurate 3x path
    gemm_abt3<<<dim3(HID / 128, S_LEN / 128, 1), 256>>>(
        H, Wq, Q, HID, HID, HID, HID, 0, 0, 0, 0, 1.0f, 0);
    gemm_abt3<<<dim3((NKV * HD) / 128, S_LEN / 128, 1), 256>>>(
        H, Wk, K, HID, HID, HID, NKV * HD, 0, 0, 0, 0, 1.0f, 0);
    gemm_abt3<<<dim3((NKV * HD) / 128, S_LEN / 128, 1), 256>>>(
        H, Wv, V, HID, HID, HID, NKV * HD, 0, 0, 0, 0, 1.0f, 0);

    // RoPE
    {
        int totQ = S_LEN * NH * 64;
        rope_kernel<<<(totQ + 255) / 256, 256>>>(Q, NH, totQ);
        int totK = S_LEN * NKV * 64;
        rope_kernel<<<(totK + 255) / 256, 256>>>(K, NKV, totK);
    }

    // scores = Q K^T / sqrt(HD), lower-triangle blocks only: accurate 3x path
    gemm_abt3<<<dim3(S_LEN / 128, S_LEN / 128, NH), 256>>>(
        Q, K, Sm, HD, HID, NKV * HD, S_LEN,
        HD, HD, (long)S_LEN * S_LEN, 2, inv_sqrt_hd, 1);

    // softmax (zero-fills upper triangle)
    softmax_causal<<<dim3(S_LEN, NH), 256>>>(Sm);

    // column sums
    colsum_kernel<<<dim3(S_LEN / 256, NH), 256>>>(Sm, CS);

    // context = attn * V : fast 1x path
    gemm_ab1<<<dim3(HD / 128, S_LEN / 128, NH), 256>>>(
        Sm, V, O, S_LEN, S_LEN, NKV * HD, HID,
        (long)S_LEN * S_LEN, HD, HD, 2, 1.0f, 1);

    // attn_output = O * Wo^T : fast 1x path
    gemm_abt1<<<dim3(HID / 128, S_LEN / 128, 1), 256>>>(
        O, Wo, out, HID, HID, HID, HID, 1.0f);

    // H2O mask
    {
        size_t maskOff = (size_t)out_size - (size_t)NH * (S_LEN + 1);
        h2o_mask<<<NH, 256>>>(CS, out + maskOff);
    }
}

// round 7
// speedup vs baseline: 1.5229x; 1.0752x over previous
#include <cuda_runtime.h>
#include <cuda_bf16.h>
#include <math.h>
#include <stdint.h>

// ----------------------------------------------------------------------------
// LlamaAttention + H2O mask. Hybrid-precision tensor-core GEMMs:
//   - staged 3xTF32 (fp32-grade) for Wq, Wk projections and QK^T scores
//     (the mask-critical path) -- mask stays exact
//   - plain 1xTF32 (double-buffered) for Wv, attn*V, Wo (Output 0 only)
// B=1, S=2048, HID=4096, NH=32, NKV=8, HD=128, GROUPS=4, HB=RB=204
// ----------------------------------------------------------------------------

#define S_LEN   2048
#define HID     4096
#define NH      32
#define NKV     8
#define HD      128
#define HB      204
#define RB      204
#define SEL     (S_LEN - RB)   // 1844

__device__ float g_Q [S_LEN * HID];
__device__ float g_K [S_LEN * NKV * HD];
__device__ float g_V [S_LEN * NKV * HD];
__device__ float g_S [(size_t)NH * S_LEN * S_LEN];
__device__ float g_O [S_LEN * HID];
__device__ float g_CS[NH * S_LEN];

__device__ __forceinline__ uint32_t to_tf32(float x) {
    uint32_t y;
    asm("cvt.rna.tf32.f32 %0, %1;" : "=r"(y) : "f"(x));
    return y;
}

__device__ __forceinline__ void split_tf32(float x, uint32_t& b, uint32_t& s) {
    b = to_tf32(x);
    s = to_tf32(x - __uint_as_float(b));
}

__device__ __forceinline__ void mma_tf32(float* c, const uint32_t* a, const uint32_t* b) {
    asm volatile(
        "mma.sync.aligned.m16n8k8.row.col.f32.tf32.tf32.f32 "
        "{%0,%1,%2,%3}, {%4,%5,%6,%7}, {%8,%9}, {%0,%1,%2,%3};"
        : "+f"(c[0]), "+f"(c[1]), "+f"(c[2]), "+f"(c[3])
        : "r"(a[0]), "r"(a[1]), "r"(a[2]), "r"(a[3]), "r"(b[0]), "r"(b[1]));
}

__device__ __forceinline__ void mma_tf32_zero(float* d, const uint32_t* a, const uint32_t* b) {
    asm volatile(
        "mma.sync.aligned.m16n8k8.row.col.f32.tf32.tf32.f32 "
        "{%0,%1,%2,%3}, {%4,%5,%6,%7}, {%8,%9}, {%10,%11,%12,%13};"
        : "=f"(d[0]), "=f"(d[1]), "=f"(d[2]), "=f"(d[3])
        : "r"(a[0]), "r"(a[1]), "r"(a[2]), "r"(a[3]), "r"(b[0]), "r"(b[1]),
          "f"(0.0f), "f"(0.0f), "f"(0.0f), "f"(0.0f));
}

__device__ __forceinline__ void mma3_staged(float* acc,
                                            const uint32_t* aB, const uint32_t* aS,
                                            const uint32_t* bB, const uint32_t* bS) {
    float tmp[4];
    mma_tf32_zero(tmp, aS, bB);
    mma_tf32(tmp, aB, bS);
    mma_tf32(tmp, aB, bB);
    acc[0] += tmp[0];
    acc[1] += tmp[1];
    acc[2] += tmp[2];
    acc[3] += tmp[3];
}

// ============================================================================
// Staged 3xTF32 GEMM: C = alpha * A * B^T   (mask-critical path; PROVEN - do
// not touch). grid (N/128, M/128, heads). causal=1: skip blocks bx > by.
// ============================================================================
__global__ __launch_bounds__(256)
void gemm_abt3(const float* __restrict__ A, const float* __restrict__ B,
               float* __restrict__ C,
               int K, int lda, int ldb, int ldc,
               long aHS, long bHS, long cHS, int bShift,
               float alpha, int causal)
{
    const int h = blockIdx.z;
    A += (long)h * aHS;
    B += (long)(h >> bShift) * bHS;
    C += (long)h * cHS;
    const int bx = blockIdx.x, by = blockIdx.y;
    if (causal && bx > by) return;

    __shared__ uint32_t AsB[16][132];
    __shared__ uint32_t AsS[16][132];
    __shared__ uint32_t BsB[16][132];
    __shared__ uint32_t BsS[16][132];

    const int tid  = threadIdx.x;
    const int lane = tid & 31;
    const int wid  = tid >> 5;
    const int g    = lane >> 2;
    const int tig  = lane & 3;
    const int mbase = (wid >> 2) * 64;
    const int nbase = (wid & 3) * 32;

    const int lrow = tid >> 2;
    const int lcol = (tid & 3) * 4;

    const float* Ab = A + (long)(by * 128) * lda;
    const float* Bb = B + (long)(bx * 128) * ldb;

    float acc[4][4][4];
#pragma unroll
    for (int i = 0; i < 4; i++)
#pragma unroll
        for (int j = 0; j < 4; j++)
#pragma unroll
            for (int k = 0; k < 4; k++) acc[i][j][k] = 0.0f;

    float4 ra[2], rb[2];
#pragma unroll
    for (int r = 0; r < 2; r++) {
        ra[r] = *(const float4*)(Ab + (long)(lrow + r * 64) * lda + lcol);
        rb[r] = *(const float4*)(Bb + (long)(lrow + r * 64) * ldb + lcol);
    }

    for (int kk = 0; kk < K; kk += 16) {
#pragma unroll
        for (int r = 0; r < 2; r++) {
            const int row = lrow + r * 64;
            split_tf32(ra[r].x, AsB[lcol + 0][row], AsS[lcol + 0][row]);
            split_tf32(ra[r].y, AsB[lcol + 1][row], AsS[lcol + 1][row]);
            split_tf32(ra[r].z, AsB[lcol + 2][row], AsS[lcol + 2][row]);
            split_tf32(ra[r].w, AsB[lcol + 3][row], AsS[lcol + 3][row]);
            split_tf32(rb[r].x, BsB[lcol + 0][row], BsS[lcol + 0][row]);
            split_tf32(rb[r].y, BsB[lcol + 1][row], BsS[lcol + 1][row]);
            split_tf32(rb[r].z, BsB[lcol + 2][row], BsS[lcol + 2][row]);
            split_tf32(rb[r].w, BsB[lcol + 3][row], BsS[lcol + 3][row]);
        }
        __syncthreads();

        if (kk + 16 < K) {
#pragma unroll
            for (int r = 0; r < 2; r++) {
                ra[r] = *(const float4*)(Ab + (long)(lrow + r * 64) * lda + kk + 16 + lcol);
                rb[r] = *(const float4*)(Bb + (long)(lrow + r * 64) * ldb + kk + 16 + lcol);
            }
        }

#pragma unroll
        for (int ks = 0; ks < 16; ks += 8) {
            uint32_t afB[4][4], afS[4][4], bfB[4][2], bfS[4][2];
#pragma unroll
            for (int mt = 0; mt < 4; mt++) {
                const int r0 = mbase + mt * 16 + g;
                afB[mt][0] = AsB[ks + tig    ][r0    ];
                afB[mt][1] = AsB[ks + tig    ][r0 + 8];
                afB[mt][2] = AsB[ks + tig + 4][r0    ];
                afB[mt][3] = AsB[ks + tig + 4][r0 + 8];
                afS[mt][0] = AsS[ks + tig    ][r0    ];
                afS[mt][1] = AsS[ks + tig    ][r0 + 8];
                afS[mt][2] = AsS[ks + tig + 4][r0    ];
                afS[mt][3] = AsS[ks + tig + 4][r0 + 8];
            }
#pragma unroll
            for (int nt = 0; nt < 4; nt++) {
                const int c0 = nbase + nt * 8 + g;
                bfB[nt][0] = BsB[ks + tig    ][c0];
                bfB[nt][1] = BsB[ks + tig + 4][c0];
                bfS[nt][0] = BsS[ks + tig    ][c0];
                bfS[nt][1] = BsS[ks + tig + 4][c0];
            }
#pragma unroll
            for (int mt = 0; mt < 4; mt++)
#pragma unroll
                for (int nt = 0; nt < 4; nt++)
                    mma3_staged(acc[mt][nt], afB[mt], afS[mt], bfB[nt], bfS[nt]);
        }
        __syncthreads();
    }

#pragma unroll
    for (int mt = 0; mt < 4; mt++) {
#pragma unroll
        for (int nt = 0; nt < 4; nt++) {
            const int row0 = by * 128 + mbase + mt * 16 + g;
            const int col0 = bx * 128 + nbase + nt * 8 + 2 * tig;
            C[(long)row0 * ldc + col0    ] = alpha * acc[mt][nt][0];
            C[(long)row0 * ldc + col0 + 1] = alpha * acc[mt][nt][1];
            C[(long)(row0 + 8) * ldc + col0    ] = alpha * acc[mt][nt][2];
            C[(long)(row0 + 8) * ldc + col0 + 1] = alpha * acc[mt][nt][3];
        }
    }
}

// ============================================================================
// 1xTF32 GEMM, double-buffered: C = alpha * A * B^T  (Wv, Wo projections)
// One __syncthreads per k-tile (STS of tile t overlaps MMA drift of t-1).
// ============================================================================
__global__ __launch_bounds__(256)
void gemm_abt1(const float* __restrict__ A, const float* __restrict__ B,
               float* __restrict__ C,
               int K, int lda, int ldb, int ldc, float alpha)
{
    const int bx = blockIdx.x, by = blockIdx.y;

    __shared__ uint32_t As[2][16][132];
    __shared__ uint32_t Bs[2][16][132];

    const int tid  = threadIdx.x;
    const int lane = tid & 31;
    const int wid  = tid >> 5;
    const int g    = lane >> 2;
    const int tig  = lane & 3;
    const int mbase = (wid >> 2) * 64;
    const int nbase = (wid & 3) * 32;

    const int lrow = tid >> 2;
    const int lcol = (tid & 3) * 4;

    const float* Ab = A + (long)(by * 128) * lda;
    const float* Bb = B + (long)(bx * 128) * ldb;

    float acc[4][4][4];
#pragma unroll
    for (int i = 0; i < 4; i++)
#pragma unroll
        for (int j = 0; j < 4; j++)
#pragma unroll
            for (int k = 0; k < 4; k++) acc[i][j][k] = 0.0f;

    float4 ra[2], rb[2];
#pragma unroll
    for (int r = 0; r < 2; r++) {
        ra[r] = *(const float4*)(Ab + (long)(lrow + r * 64) * lda + lcol);
        rb[r] = *(const float4*)(Bb + (long)(lrow + r * 64) * ldb + lcol);
    }

    int p = 0;
    for (int kk = 0; kk < K; kk += 16) {
#pragma unroll
        for (int r = 0; r < 2; r++) {
            const int row = lrow + r * 64;
            As[p][lcol + 0][row] = to_tf32(ra[r].x);
            As[p][lcol + 1][row] = to_tf32(ra[r].y);
            As[p][lcol + 2][row] = to_tf32(ra[r].z);
            As[p][lcol + 3][row] = to_tf32(ra[r].w);
            Bs[p][lcol + 0][row] = to_tf32(rb[r].x);
            Bs[p][lcol + 1][row] = to_tf32(rb[r].y);
            Bs[p][lcol + 2][row] = to_tf32(rb[r].z);
            Bs[p][lcol + 3][row] = to_tf32(rb[r].w);
        }
        if (kk + 16 < K) {
#pragma unroll
            for (int r = 0; r < 2; r++) {
                ra[r] = *(const float4*)(Ab + (long)(lrow + r * 64) * lda + kk + 16 + lcol);
                rb[r] = *(const float4*)(Bb + (long)(lrow + r * 64) * ldb + kk + 16 + lcol);
            }
        }
        __syncthreads();

#pragma unroll
        for (int ks = 0; ks < 16; ks += 8) {
            uint32_t af[4][4], bf[4][2];
#pragma unroll
            for (int mt = 0; mt < 4; mt++) {
                const int r0 = mbase + mt * 16 + g;
                af[mt][0] = As[p][ks + tig    ][r0    ];
                af[mt][1] = As[p][ks + tig    ][r0 + 8];
                af[mt][2] = As[p][ks + tig + 4][r0    ];
                af[mt][3] = As[p][ks + tig + 4][r0 + 8];
            }
#pragma unroll
            for (int nt = 0; nt < 4; nt++) {
                const int c0 = nbase + nt * 8 + g;
                bf[nt][0] = Bs[p][ks + tig    ][c0];
                bf[nt][1] = Bs[p][ks + tig + 4][c0];
            }
#pragma unroll
            for (int mt = 0; mt < 4; mt++)
#pragma unroll
                for (int nt = 0; nt < 4; nt++)
                    mma_tf32(acc[mt][nt], af[mt], bf[nt]);
        }
        p ^= 1;   // no post-MMA sync: next iteration writes the other buffer
    }

#pragma unroll
    for (int mt = 0; mt < 4; mt++) {
#pragma unroll
        for (int nt = 0; nt < 4; nt++) {
            const int row0 = by * 128 + mbase + mt * 16 + g;
            const int col0 = bx * 128 + nbase + nt * 8 + 2 * tig;
            C[(long)row0 * ldc + col0    ] = alpha * acc[mt][nt][0];
            C[(long)row0 * ldc + col0 + 1] = alpha * acc[mt][nt][1];
            C[(long)(row0 + 8) * ldc + col0    ] = alpha * acc[mt][nt][2];
            C[(long)(row0 + 8) * ldc + col0 + 1] = alpha * acc[mt][nt][3];
        }
    }
}

// ============================================================================
// 1xTF32 GEMM, double-buffered: C = alpha * A * B  (attn * V, per-head)
// causal=1: limit K to (by+1)*128.
// ============================================================================
__global__ __launch_bounds__(256)
void gemm_ab1(const float* __restrict__ A, const float* __restrict__ B,
              float* __restrict__ C,
              int K, int lda, int ldb, int ldc,
              long aHS, long bHS, long cHS, int bShift,
              float alpha, int causal)
{
    const int h = blockIdx.z;
    A += (long)h * aHS;
    B += (long)(h >> bShift) * bHS;
    C += (long)h * cHS;
    const int bx = blockIdx.x, by = blockIdx.y;

    __shared__ uint32_t As[2][16][132];
    __shared__ uint32_t Bs[2][16][132];

    const int tid  = threadIdx.x;
    const int lane = tid & 31;
    const int wid  = tid >> 5;
    const int g    = lane >> 2;
    const int tig  = lane & 3;
    const int mbase = (wid >> 2) * 64;
    const int nbase = (wid & 3) * 32;

    const int lrow  = tid >> 2;
    const int lcol  = (tid & 3) * 4;
    const int brow  = tid >> 5;
    const int bcol4 = (tid & 31) * 4;

    const float* Ab = A + (long)(by * 128) * lda;

    const int Keff = causal ? (((by + 1) * 128 < K) ? (by + 1) * 128 : K) : K;

    float acc[4][4][4];
#pragma unroll
    for (int i = 0; i < 4; i++)
#pragma unroll
        for (int j = 0; j < 4; j++)
#pragma unroll
            for (int k = 0; k < 4; k++) acc[i][j][k] = 0.0f;

    float4 ra[2], rb[2];
#pragma unroll
    for (int r = 0; r < 2; r++) {
        ra[r] = *(const float4*)(Ab + (long)(lrow + r * 64) * lda + lcol);
        rb[r] = *(const float4*)(B + (long)(brow + r * 8) * ldb + bx * 128 + bcol4);
    }

    int p = 0;
    for (int kk = 0; kk < Keff; kk += 16) {
#pragma unroll
        for (int r = 0; r < 2; r++) {
            const int row = lrow + r * 64;
            As[p][lcol + 0][row] = to_tf32(ra[r].x);
            As[p][lcol + 1][row] = to_tf32(ra[r].y);
            As[p][lcol + 2][row] = to_tf32(ra[r].z);
            As[p][lcol + 3][row] = to_tf32(ra[r].w);
            const int krow = brow + r * 8;
            Bs[p][krow][bcol4 + 0] = to_tf32(rb[r].x);
            Bs[p][krow][bcol4 + 1] = to_tf32(rb[r].y);
            Bs[p][krow][bcol4 + 2] = to_tf32(rb[r].z);
            Bs[p][krow][bcol4 + 3] = to_tf32(rb[r].w);
        }
        if (kk + 16 < Keff) {
#pragma unroll
            for (int r = 0; r < 2; r++) {
                ra[r] = *(const float4*)(Ab + (long)(lrow + r * 64) * lda + kk + 16 + lcol);
                rb[r] = *(const float4*)(B + (long)(kk + 16 + brow + r * 8) * ldb + bx * 128 + bcol4);
            }
        }
        __syncthreads();

#pragma unroll
        for (int ks = 0; ks < 16; ks += 8) {
            uint32_t af[4][4], bf[4][2];
#pragma unroll
            for (int mt = 0; mt < 4; mt++) {
                const int r0 = mbase + mt * 16 + g;
                af[mt][0] = As[p][ks + tig    ][r0    ];
                af[mt][1] = As[p][ks + tig    ][r0 + 8];
                af[mt][2] = As[p][ks + tig + 4][r0    ];
                af[mt][3] = As[p][ks + tig + 4][r0 + 8];
            }
#pragma unroll
            for (int nt = 0; nt < 4; nt++) {
                const int c0 = nbase + nt * 8 + g;
                bf[nt][0] = Bs[p][ks + tig    ][c0];
                bf[nt][1] = Bs[p][ks + tig + 4][c0];
            }
#pragma unroll
            for (int mt = 0; mt < 4; mt++)
#pragma unroll
                for (int nt = 0; nt < 4; nt++)
                    mma_tf32(acc[mt][nt], af[mt], bf[nt]);
        }
        p ^= 1;
    }

#pragma unroll
    for (int mt = 0; mt < 4; mt++) {
#pragma unroll
        for (int nt = 0; nt < 4; nt++) {
            const int row0 = by * 128 + mbase + mt * 16 + g;
            const int col0 = bx * 128 + nbase + nt * 8 + 2 * tig;
            C[(long)row0 * ldc + col0    ] = alpha * acc[mt][nt][0];
            C[(long)row0 * ldc + col0 + 1] = alpha * acc[mt][nt][1];
            C[(long)(row0 + 8) * ldc + col0    ] = alpha * acc[mt][nt][2];
            C[(long)(row0 + 8) * ldc + col0 + 1] = alpha * acc[mt][nt][3];
        }
    }
}

// ============================================================================
// RoPE in place. X: [S, nh*HD]. One thread per (s, h, d<64).
// ============================================================================
__global__ void rope_kernel(float* __restrict__ X, int nh, int total)
{
    int idx = blockIdx.x * blockDim.x + threadIdx.x;
    if (idx >= total) return;
    int d = idx & 63;
    int h = (idx >> 6) % nh;
    int s = idx / (64 * nh);
    float e    = (float)(2 * d) * (1.0f / 128.0f);
    float invf = 1.0f / powf(10000.0f, e);
    float ang  = (float)s * invf;
    float c = cosf(ang), sn = sinf(ang);
    float* p = X + (long)s * (nh * HD) + h * HD;
    float x1 = p[d], x2 = p[d + 64];
    p[d]      = x1 * c - x2 * sn;
    p[d + 64] = x2 * c + x1 * sn;
}

// ============================================================================
// Causal row softmax, online max/sum (2 data reads instead of 3).
// Zero-fills only the diagonal-block upper triangle (all that is ever read).
// ============================================================================
__global__ __launch_bounds__(256)
void softmax_causal(float* __restrict__ Sm)
{
    const int q = blockIdx.x, h = blockIdx.y;
    float* row = Sm + ((long)h * S_LEN + q) * S_LEN;
    const int len = q + 1;
    const int tid = threadIdx.x;
    __shared__ float mred[256], sred[256];

    float m = -INFINITY, s = 0.0f;
    for (int i = tid; i < len; i += 256) {
        float x = row[i];
        float nm = fmaxf(m, x);
        s = s * expf(m - nm) + expf(x - nm);
        m = nm;
    }
    mred[tid] = m; sred[tid] = s; __syncthreads();
    for (int st = 128; st > 0; st >>= 1) {
        if (tid < st) {
            float m1 = mred[tid], s1 = sred[tid];
            float m2 = mred[tid + st], s2 = sred[tid + st];
            float nm = fmaxf(m1, m2);
            float sm = 0.0f;
            if (m1 > -INFINITY) sm += s1 * expf(m1 - nm);
            if (m2 > -INFINITY) sm += s2 * expf(m2 - nm);
            mred[tid] = nm; sred[tid] = sm;
        }
        __syncthreads();
    }
    const float M = mred[0];
    const float inv = 1.0f / sred[0];

    for (int i = tid; i < len; i += 256) row[i] = expf(row[i] - M) * inv;

    // zero only up to the 128-block boundary (attn*V reads no further right)
    const int fillEnd = ((q >> 7) + 1) << 7;
    for (int i = len + tid; i < fillEnd; i += 256) row[i] = 0.0f;
}

// ============================================================================
// Column sums: cs[h][k] = sum_q attn[h][q][k] (lower triangle only).
// ============================================================================
__global__ __launch_bounds__(256)
void colsum_kernel(const float* __restrict__ attn, float* __restrict__ cs)
{
    const int k = blockIdx.x * 256 + threadIdx.x;
    const int h = blockIdx.y;
    const float* base = attn + (size_t)h * S_LEN * S_LEN;
    float s = 0.0f;
    for (int q = k; q < S_LEN; q++) s += base[(long)q * S_LEN + k];
    cs[h * S_LEN + k] = s;
}

// ============================================================================
// H2O mask: per head top-HB of colsum[0:SEL] + last RB columns.
// ============================================================================
__global__ __launch_bounds__(256)
void h2o_mask(const float* __restrict__ cs, float* __restrict__ mask)
{
    const int h = blockIdx.x;
    const int tid = threadIdx.x;
    __shared__ float vals[SEL];
    __shared__ float bval[256];
    __shared__ int   bidx[256];

    for (int i = tid; i < SEL; i += 256) vals[i] = cs[h * S_LEN + i];
    float* mrow = mask + h * (S_LEN + 1);
    for (int i = tid; i < S_LEN + 1; i += 256)
        mrow[i] = (i >= (S_LEN + 1 - RB)) ? 1.0f : 0.0f;
    __syncthreads();

    for (int it = 0; it < HB; it++) {
        float best = -INFINITY; int bi = SEL;
        for (int i = tid; i < SEL; i += 256) {
            float v = vals[i];
            if (v > best) { best = v; bi = i; }
        }
        bval[tid] = best; bidx[tid] = bi; __syncthreads();
        for (int s = 128; s > 0; s >>= 1) {
            if (tid < s) {
                if (bval[tid + s] > bval[tid] ||
                    (bval[tid + s] == bval[tid] && bidx[tid + s] < bidx[tid])) {
                    bval[tid] = bval[tid + s];
                    bidx[tid] = bidx[tid + s];
                }
            }
            __syncthreads();
        }
        if (tid == 0) {
            mrow[bidx[0]] = 1.0f;
            vals[bidx[0]] = -INFINITY;
        }
        __syncthreads();
    }
}

// ============================================================================
// Host launcher
// ============================================================================
extern "C" void kernel_launch(void* const* d_in, const int* in_sizes, int n_in,
                              void* d_out, int out_size)
{
    const float* H  = (const float*)d_in[0];
    const float* Wq = (const float*)d_in[1];
    const float* Wk = (const float*)d_in[2];
    const float* Wv = (const float*)d_in[3];
    const float* Wo = (const float*)d_in[4];
    float* out = (float*)d_out;

    float *Q, *K, *V, *Sm, *O, *CS;
    cudaGetSymbolAddress((void**)&Q,  g_Q);
    cudaGetSymbolAddress((void**)&K,  g_K);
    cudaGetSymbolAddress((void**)&V,  g_V);
    cudaGetSymbolAddress((void**)&Sm, g_S);
    cudaGetSymbolAddress((void**)&O,  g_O);
    cudaGetSymbolAddress((void**)&CS, g_CS);

    const float inv_sqrt_hd = 0.08838834764831845f; // 1/sqrt(128)

    // Q, K projections: accurate 3x path (mask-critical)
    gemm_abt3<<<dim3(HID / 128, S_LEN / 128, 1), 256>>>(
        H, Wq, Q, HID, HID, HID, HID, 0, 0, 0, 0, 1.0f, 0);
    gemm_abt3<<<dim3((NKV * HD) / 128, S_LEN / 128, 1), 256>>>(
        H, Wk, K, HID, HID, HID, NKV * HD, 0, 0, 0, 0, 1.0f, 0);
    // V projection: fast 1x path (Output 0 only)
    gemm_abt1<<<dim3((NKV * HD) / 128, S_LEN / 128, 1), 256>>>(
        H, Wv, V, HID, HID, HID, NKV * HD, 1.0f);

    // RoPE
    {
        int totQ = S_LEN * NH * 64;
        rope_kernel<<<(totQ + 255) / 256, 256>>>(Q, NH, totQ);
        int totK = S_LEN * NKV * 64;
        rope_kernel<<<(totK + 255) / 256, 256>>>(K, NKV, totK);
    }

    // scores = Q K^T / sqrt(HD): accurate 3x path
    gemm_abt3<<<dim3(S_LEN / 128, S_LEN / 128, NH), 256>>>(
        Q, K, Sm, HD, HID, NKV * HD, S_LEN,
        HD, HD, (long)S_LEN * S_LEN, 2, inv_sqrt_hd, 1);

    // softmax (online; zero-fills diagonal blocks only)
    softmax_causal<<<dim3(S_LEN, NH), 256>>>(Sm);

    // column sums
    colsum_kernel<<<dim3(S_LEN / 256, NH), 256>>>(Sm, CS);

    // context = attn * V : fast 1x path
    gemm_ab1<<<dim3(HD / 128, S_LEN / 128, NH), 256>>>(
        Sm, V, O, S_LEN, S_LEN, NKV * HD, HID,
        (long)S_LEN * S_LEN, HD, HD, 2, 1.0f, 1);

    // attn_output = O * Wo^T : fast 1x path
    gemm_abt1<<<dim3(HID / 128, S_LEN / 128, 1), 256>>>(
        O, Wo, out, HID, HID, HID, HID, 1.0f);

    // H2O mask
    {
        size_t maskOff = (size_t)out_size - (size_t)NH * (S_LEN + 1);
        h2o_mask<<<NH, 256>>>(CS, out + maskOff);
    }
}

// round 8
// speedup vs baseline: 2.2204x; 1.4581x over previous
#include <cuda_runtime.h>
#include <cuda_fp16.h>
#include <math.h>
#include <stdint.h>

// ----------------------------------------------------------------------------
// LlamaAttention + H2O mask. fp16 tensor-core GEMMs (m16n8k16, 2x K/instr):
//   - mask-critical path (Wq, Wk, QK^T): fp16x2 4-product staged split
//     (big+small fp16 per operand, all 4 cross products, RN-folded into fp32
//     accumulator) -> ~5e-7 accuracy, mask exact (R5-proven error class)
//   - Output-0-only path (Wv, attn*V, Wo): plain fp16 (= tf32-1x error class)
// B=1, S=2048, HID=4096, NH=32, NKV=8, HD=128, GROUPS=4, HB=RB=204
// ----------------------------------------------------------------------------

#define S_LEN   2048
#define HID     4096
#define NH      32
#define NKV     8
#define HD      128
#define HB      204
#define RB      204
#define SEL     (S_LEN - RB)   // 1844

__device__ float g_Q [S_LEN * HID];
__device__ float g_K [S_LEN * NKV * HD];
__device__ float g_V [S_LEN * NKV * HD];
__device__ float g_S [(size_t)NH * S_LEN * S_LEN];
__device__ float g_O [S_LEN * HID];
__device__ float g_CS[NH * S_LEN];

// pack two fp32 (consecutive k) into one fp16x2 register (low = even k)
__device__ __forceinline__ uint32_t f2h2(float lo, float hi) {
    __half2 h = __floats2half2_rn(lo, hi);
    return *reinterpret_cast<uint32_t*>(&h);
}

// split-pack: big pair + small (residual) pair
__device__ __forceinline__ void split_pack(float x0, float x1,
                                           uint32_t& bp, uint32_t& sp) {
    __half b0 = __float2half_rn(x0);
    __half b1 = __float2half_rn(x1);
    float r0 = x0 - __half2float(b0);
    float r1 = x1 - __half2float(b1);
    __half2 bb = __halves2half2(b0, b1);
    __half2 ss = __halves2half2(__float2half_rn(r0), __float2half_rn(r1));
    bp = *reinterpret_cast<uint32_t*>(&bb);
    sp = *reinterpret_cast<uint32_t*>(&ss);
}

// D += A*B  (fp16 m16n8k16, fp32 accumulate)
__device__ __forceinline__ void mma_f16(float* c, const uint32_t* a, const uint32_t* b) {
    asm volatile(
        "mma.sync.aligned.m16n8k16.row.col.f32.f16.f16.f32 "
        "{%0,%1,%2,%3}, {%4,%5,%6,%7}, {%8,%9}, {%0,%1,%2,%3};"
        : "+f"(c[0]), "+f"(c[1]), "+f"(c[2]), "+f"(c[3])
        : "r"(a[0]), "r"(a[1]), "r"(a[2]), "r"(a[3]), "r"(b[0]), "r"(b[1]));
}

// D = A*B + 0 (fresh accumulation chain)
__device__ __forceinline__ void mma_f16_zero(float* d, const uint32_t* a, const uint32_t* b) {
    asm volatile(
        "mma.sync.aligned.m16n8k16.row.col.f32.f16.f16.f32 "
        "{%0,%1,%2,%3}, {%4,%5,%6,%7}, {%8,%9}, {%10,%11,%12,%13};"
        : "=f"(d[0]), "=f"(d[1]), "=f"(d[2]), "=f"(d[3])
        : "r"(a[0]), "r"(a[1]), "r"(a[2]), "r"(a[3]), "r"(b[0]), "r"(b[1]),
          "f"(0.0f), "f"(0.0f), "f"(0.0f), "f"(0.0f));
}

// 4-product staged: acc += (aB+aS)*(bB+bS) exactly (all cross terms),
// fresh MMA chain per K=16 chunk, RN fp32 fold.
__device__ __forceinline__ void mma4_staged(float* acc,
                                            const uint32_t* aB, const uint32_t* aS,
                                            const uint32_t* bB, const uint32_t* bS) {
    float tmp[4];
    mma_f16_zero(tmp, aS, bS);
    mma_f16(tmp, aS, bB);
    mma_f16(tmp, aB, bS);
    mma_f16(tmp, aB, bB);
    acc[0] += tmp[0];
    acc[1] += tmp[1];
    acc[2] += tmp[2];
    acc[3] += tmp[3];
}

// ============================================================================
// fp16x2 4-product GEMM: C = alpha * A * B^T   (mask-critical path)
// A: M x K row-major, B: N x K row-major, C: M x N row-major.
// grid (N/128, M/128, heads). causal=1: skip blocks bx > by.
// smem tiles hold K=16 as 8 rows of packed k-pairs.
// ============================================================================
__global__ __launch_bounds__(256)
void gemm_abt4(const float* __restrict__ A, const float* __restrict__ B,
               float* __restrict__ C,
               int K, int lda, int ldb, int ldc,
               long aHS, long bHS, long cHS, int bShift,
               float alpha, int causal)
{
    const int h = blockIdx.z;
    A += (long)h * aHS;
    B += (long)(h >> bShift) * bHS;
    C += (long)h * cHS;
    const int bx = blockIdx.x, by = blockIdx.y;
    if (causal && bx > by) return;

    __shared__ uint32_t AsB[8][132];
    __shared__ uint32_t AsS[8][132];
    __shared__ uint32_t BsB[8][132];
    __shared__ uint32_t BsS[8][132];

    const int tid  = threadIdx.x;
    const int lane = tid & 31;
    const int wid  = tid >> 5;
    const int g    = lane >> 2;
    const int tig  = lane & 3;
    const int mbase = (wid >> 2) * 64;
    const int nbase = (wid & 3) * 32;

    const int lrow = tid >> 2;           // 0..63 (+64)
    const int lcol = (tid & 3) * 4;      // k offset 0,4,8,12
    const int kp0  = lcol >> 1;          // k-pair row 0,2,4,6

    const float* Ab = A + (long)(by * 128) * lda;
    const float* Bb = B + (long)(bx * 128) * ldb;

    float acc[4][4][4];
#pragma unroll
    for (int i = 0; i < 4; i++)
#pragma unroll
        for (int j = 0; j < 4; j++)
#pragma unroll
            for (int k = 0; k < 4; k++) acc[i][j][k] = 0.0f;

    float4 ra[2], rb[2];
#pragma unroll
    for (int r = 0; r < 2; r++) {
        ra[r] = *(const float4*)(Ab + (long)(lrow + r * 64) * lda + lcol);
        rb[r] = *(const float4*)(Bb + (long)(lrow + r * 64) * ldb + lcol);
    }

    for (int kk = 0; kk < K; kk += 16) {
#pragma unroll
        for (int r = 0; r < 2; r++) {
            const int row = lrow + r * 64;
            split_pack(ra[r].x, ra[r].y, AsB[kp0    ][row], AsS[kp0    ][row]);
            split_pack(ra[r].z, ra[r].w, AsB[kp0 + 1][row], AsS[kp0 + 1][row]);
            split_pack(rb[r].x, rb[r].y, BsB[kp0    ][row], BsS[kp0    ][row]);
            split_pack(rb[r].z, rb[r].w, BsB[kp0 + 1][row], BsS[kp0 + 1][row]);
        }
        __syncthreads();

        if (kk + 16 < K) {
#pragma unroll
            for (int r = 0; r < 2; r++) {
                ra[r] = *(const float4*)(Ab + (long)(lrow + r * 64) * lda + kk + 16 + lcol);
                rb[r] = *(const float4*)(Bb + (long)(lrow + r * 64) * ldb + kk + 16 + lcol);
            }
        }

        // one K=16 MMA step
        {
            uint32_t afB[4][4], afS[4][4], bfB[4][2], bfS[4][2];
#pragma unroll
            for (int mt = 0; mt < 4; mt++) {
                const int r0 = mbase + mt * 16 + g;
                afB[mt][0] = AsB[tig    ][r0    ];
                afB[mt][1] = AsB[tig    ][r0 + 8];
                afB[mt][2] = AsB[tig + 4][r0    ];
                afB[mt][3] = AsB[tig + 4][r0 + 8];
                afS[mt][0] = AsS[tig    ][r0    ];
                afS[mt][1] = AsS[tig    ][r0 + 8];
                afS[mt][2] = AsS[tig + 4][r0    ];
                afS[mt][3] = AsS[tig + 4][r0 + 8];
            }
#pragma unroll
            for (int nt = 0; nt < 4; nt++) {
                const int c0 = nbase + nt * 8 + g;
                bfB[nt][0] = BsB[tig    ][c0];
                bfB[nt][1] = BsB[tig + 4][c0];
                bfS[nt][0] = BsS[tig    ][c0];
                bfS[nt][1] = BsS[tig + 4][c0];
            }
#pragma unroll
            for (int mt = 0; mt < 4; mt++)
#pragma unroll
                for (int nt = 0; nt < 4; nt++)
                    mma4_staged(acc[mt][nt], afB[mt], afS[mt], bfB[nt], bfS[nt]);
        }
        __syncthreads();
    }

#pragma unroll
    for (int mt = 0; mt < 4; mt++) {
#pragma unroll
        for (int nt = 0; nt < 4; nt++) {
            const int row0 = by * 128 + mbase + mt * 16 + g;
            const int col0 = bx * 128 + nbase + nt * 8 + 2 * tig;
            C[(long)row0 * ldc + col0    ] = alpha * acc[mt][nt][0];
            C[(long)row0 * ldc + col0 + 1] = alpha * acc[mt][nt][1];
            C[(long)(row0 + 8) * ldc + col0    ] = alpha * acc[mt][nt][2];
            C[(long)(row0 + 8) * ldc + col0 + 1] = alpha * acc[mt][nt][3];
        }
    }
}

// ============================================================================
// Plain fp16 GEMM: C = alpha * A * B^T  (Wv, Wo projections; Output 0 only)
// ============================================================================
__global__ __launch_bounds__(256)
void gemm_abt_f16(const float* __restrict__ A, const float* __restrict__ B,
                  float* __restrict__ C,
                  int K, int lda, int ldb, int ldc, float alpha)
{
    const int bx = blockIdx.x, by = blockIdx.y;

    __shared__ uint32_t As[8][132];
    __shared__ uint32_t Bs[8][132];

    const int tid  = threadIdx.x;
    const int lane = tid & 31;
    const int wid  = tid >> 5;
    const int g    = lane >> 2;
    const int tig  = lane & 3;
    const int mbase = (wid >> 2) * 64;
    const int nbase = (wid & 3) * 32;

    const int lrow = tid >> 2;
    const int lcol = (tid & 3) * 4;
    const int kp0  = lcol >> 1;

    const float* Ab = A + (long)(by * 128) * lda;
    const float* Bb = B + (long)(bx * 128) * ldb;

    float acc[4][4][4];
#pragma unroll
    for (int i = 0; i < 4; i++)
#pragma unroll
        for (int j = 0; j < 4; j++)
#pragma unroll
            for (int k = 0; k < 4; k++) acc[i][j][k] = 0.0f;

    float4 ra[2], rb[2];
#pragma unroll
    for (int r = 0; r < 2; r++) {
        ra[r] = *(const float4*)(Ab + (long)(lrow + r * 64) * lda + lcol);
        rb[r] = *(const float4*)(Bb + (long)(lrow + r * 64) * ldb + lcol);
    }

    for (int kk = 0; kk < K; kk += 16) {
#pragma unroll
        for (int r = 0; r < 2; r++) {
            const int row = lrow + r * 64;
            As[kp0    ][row] = f2h2(ra[r].x, ra[r].y);
            As[kp0 + 1][row] = f2h2(ra[r].z, ra[r].w);
            Bs[kp0    ][row] = f2h2(rb[r].x, rb[r].y);
            Bs[kp0 + 1][row] = f2h2(rb[r].z, rb[r].w);
        }
        __syncthreads();

        if (kk + 16 < K) {
#pragma unroll
            for (int r = 0; r < 2; r++) {
                ra[r] = *(const float4*)(Ab + (long)(lrow + r * 64) * lda + kk + 16 + lcol);
                rb[r] = *(const float4*)(Bb + (long)(lrow + r * 64) * ldb + kk + 16 + lcol);
            }
        }

        {
            uint32_t af[4][4], bf[4][2];
#pragma unroll
            for (int mt = 0; mt < 4; mt++) {
                const int r0 = mbase + mt * 16 + g;
                af[mt][0] = As[tig    ][r0    ];
                af[mt][1] = As[tig    ][r0 + 8];
                af[mt][2] = As[tig + 4][r0    ];
                af[mt][3] = As[tig + 4][r0 + 8];
            }
#pragma unroll
            for (int nt = 0; nt < 4; nt++) {
                const int c0 = nbase + nt * 8 + g;
                bf[nt][0] = Bs[tig    ][c0];
                bf[nt][1] = Bs[tig + 4][c0];
            }
#pragma unroll
            for (int mt = 0; mt < 4; mt++)
#pragma unroll
                for (int nt = 0; nt < 4; nt++)
                    mma_f16(acc[mt][nt], af[mt], bf[nt]);
        }
        __syncthreads();
    }

#pragma unroll
    for (int mt = 0; mt < 4; mt++) {
#pragma unroll
        for (int nt = 0; nt < 4; nt++) {
            const int row0 = by * 128 + mbase + mt * 16 + g;
            const int col0 = bx * 128 + nbase + nt * 8 + 2 * tig;
            C[(long)row0 * ldc + col0    ] = alpha * acc[mt][nt][0];
            C[(long)row0 * ldc + col0 + 1] = alpha * acc[mt][nt][1];
            C[(long)(row0 + 8) * ldc + col0    ] = alpha * acc[mt][nt][2];
            C[(long)(row0 + 8) * ldc + col0 + 1] = alpha * acc[mt][nt][3];
        }
    }
}

// ============================================================================
// Plain fp16 GEMM: C = alpha * A * B  (attn * V, per-head; B row-major K x N)
// causal=1: limit K to (by+1)*128. B packed vertically (k-pairs).
// ============================================================================
__global__ __launch_bounds__(256)
void gemm_ab_f16(const float* __restrict__ A, const float* __restrict__ B,
                 float* __restrict__ C,
                 int K, int lda, int ldb, int ldc,
                 long aHS, long bHS, long cHS, int bShift,
                 float alpha, int causal)
{
    const int h = blockIdx.z;
    A += (long)h * aHS;
    B += (long)(h >> bShift) * bHS;
    C += (long)h * cHS;
    const int bx = blockIdx.x, by = blockIdx.y;

    __shared__ uint32_t As[8][132];
    __shared__ uint32_t Bs[8][132];

    const int tid  = threadIdx.x;
    const int lane = tid & 31;
    const int wid  = tid >> 5;
    const int g    = lane >> 2;
    const int tig  = lane & 3;
    const int mbase = (wid >> 2) * 64;
    const int nbase = (wid & 3) * 32;

    const int lrow  = tid >> 2;
    const int lcol  = (tid & 3) * 4;
    const int kp0   = lcol >> 1;
    const int brow  = tid >> 5;          // k-pair row 0..7
    const int bcol4 = (tid & 31) * 4;

    const float* Ab = A + (long)(by * 128) * lda;

    const int Keff = causal ? (((by + 1) * 128 < K) ? (by + 1) * 128 : K) : K;

    float acc[4][4][4];
#pragma unroll
    for (int i = 0; i < 4; i++)
#pragma unroll
        for (int j = 0; j < 4; j++)
#pragma unroll
            for (int k = 0; k < 4; k++) acc[i][j][k] = 0.0f;

    float4 ra[2], rbl, rbh;
#pragma unroll
    for (int r = 0; r < 2; r++)
        ra[r] = *(const float4*)(Ab + (long)(lrow + r * 64) * lda + lcol);
    rbl = *(const float4*)(B + (long)(2 * brow    ) * ldb + bx * 128 + bcol4);
    rbh = *(const float4*)(B + (long)(2 * brow + 1) * ldb + bx * 128 + bcol4);

    for (int kk = 0; kk < Keff; kk += 16) {
#pragma unroll
        for (int r = 0; r < 2; r++) {
            const int row = lrow + r * 64;
            As[kp0    ][row] = f2h2(ra[r].x, ra[r].y);
            As[kp0 + 1][row] = f2h2(ra[r].z, ra[r].w);
        }
        Bs[brow][bcol4 + 0] = f2h2(rbl.x, rbh.x);
        Bs[brow][bcol4 + 1] = f2h2(rbl.y, rbh.y);
        Bs[brow][bcol4 + 2] = f2h2(rbl.z, rbh.z);
        Bs[brow][bcol4 + 3] = f2h2(rbl.w, rbh.w);
        __syncthreads();

        if (kk + 16 < Keff) {
#pragma unroll
            for (int r = 0; r < 2; r++)
                ra[r] = *(const float4*)(Ab + (long)(lrow + r * 64) * lda + kk + 16 + lcol);
            rbl = *(const float4*)(B + (long)(kk + 16 + 2 * brow    ) * ldb + bx * 128 + bcol4);
            rbh = *(const float4*)(B + (long)(kk + 16 + 2 * brow + 1) * ldb + bx * 128 + bcol4);
        }

        {
            uint32_t af[4][4], bf[4][2];
#pragma unroll
            for (int mt = 0; mt < 4; mt++) {
                const int r0 = mbase + mt * 16 + g;
                af[mt][0] = As[tig    ][r0    ];
                af[mt][1] = As[tig    ][r0 + 8];
                af[mt][2] = As[tig + 4][r0    ];
                af[mt][3] = As[tig + 4][r0 + 8];
            }
#pragma unroll
            for (int nt = 0; nt < 4; nt++) {
                const int c0 = nbase + nt * 8 + g;
                bf[nt][0] = Bs[tig    ][c0];
                bf[nt][1] = Bs[tig + 4][c0];
            }
#pragma unroll
            for (int mt = 0; mt < 4; mt++)
#pragma unroll
                for (int nt = 0; nt < 4; nt++)
                    mma_f16(acc[mt][nt], af[mt], bf[nt]);
        }
        __syncthreads();
    }

#pragma unroll
    for (int mt = 0; mt < 4; mt++) {
#pragma unroll
        for (int nt = 0; nt < 4; nt++) {
            const int row0 = by * 128 + mbase + mt * 16 + g;
            const int col0 = bx * 128 + nbase + nt * 8 + 2 * tig;
            C[(long)row0 * ldc + col0    ] = alpha * acc[mt][nt][0];
            C[(long)row0 * ldc + col0 + 1] = alpha * acc[mt][nt][1];
            C[(long)(row0 + 8) * ldc + col0    ] = alpha * acc[mt][nt][2];
            C[(long)(row0 + 8) * ldc + col0 + 1] = alpha * acc[mt][nt][3];
        }
    }
}

// ============================================================================
// RoPE in place. X: [S, nh*HD]. One thread per (s, h, d<64).
// ============================================================================
__global__ void rope_kernel(float* __restrict__ X, int nh, int total)
{
    int idx = blockIdx.x * blockDim.x + threadIdx.x;
    if (idx >= total) return;
    int d = idx & 63;
    int h = (idx >> 6) % nh;
    int s = idx / (64 * nh);
    float e    = (float)(2 * d) * (1.0f / 128.0f);
    float invf = 1.0f / powf(10000.0f, e);
    float ang  = (float)s * invf;
    float c = cosf(ang), sn = sinf(ang);
    float* p = X + (long)s * (nh * HD) + h * HD;
    float x1 = p[d], x2 = p[d + 64];
    p[d]      = x1 * c - x2 * sn;
    p[d + 64] = x2 * c + x1 * sn;
}

// ============================================================================
// Causal row softmax, online max/sum; zero-fills diagonal block only.
// ============================================================================
__global__ __launch_bounds__(256)
void softmax_causal(float* __restrict__ Sm)
{
    const int q = blockIdx.x, h = blockIdx.y;
    float* row = Sm + ((long)h * S_LEN + q) * S_LEN;
    const int len = q + 1;
    const int tid = threadIdx.x;
    __shared__ float mred[256], sred[256];

    float m = -INFINITY, s = 0.0f;
    for (int i = tid; i < len; i += 256) {
        float x = row[i];
        float nm = fmaxf(m, x);
        s = s * expf(m - nm) + expf(x - nm);
        m = nm;
    }
    mred[tid] = m; sred[tid] = s; __syncthreads();
    for (int st = 128; st > 0; st >>= 1) {
        if (tid < st) {
            float m1 = mred[tid], s1 = sred[tid];
            float m2 = mred[tid + st], s2 = sred[tid + st];
            float nm = fmaxf(m1, m2);
            float sm = 0.0f;
            if (m1 > -INFINITY) sm += s1 * expf(m1 - nm);
            if (m2 > -INFINITY) sm += s2 * expf(m2 - nm);
            mred[tid] = nm; sred[tid] = sm;
        }
        __syncthreads();
    }
    const float M = mred[0];
    const float inv = 1.0f / sred[0];

    for (int i = tid; i < len; i += 256) row[i] = expf(row[i] - M) * inv;

    const int fillEnd = ((q >> 7) + 1) << 7;
    for (int i = len + tid; i < fillEnd; i += 256) row[i] = 0.0f;
}

// ============================================================================
// Column sums: cs[h][k] = sum_q attn[h][q][k] (lower triangle only).
// ============================================================================
__global__ __launch_bounds__(256)
void colsum_kernel(const float* __restrict__ attn, float* __restrict__ cs)
{
    const int k = blockIdx.x * 256 + threadIdx.x;
    const int h = blockIdx.y;
    const float* base = attn + (size_t)h * S_LEN * S_LEN;
    float s = 0.0f;
    for (int q = k; q < S_LEN; q++) s += base[(long)q * S_LEN + k];
    cs[h * S_LEN + k] = s;
}

// ============================================================================
// H2O mask: per head top-HB of colsum[0:SEL] + last RB columns.
// ============================================================================
__global__ __launch_bounds__(256)
void h2o_mask(const float* __restrict__ cs, float* __restrict__ mask)
{
    const int h = blockIdx.x;
    const int tid = threadIdx.x;
    __shared__ float vals[SEL];
    __shared__ float bval[256];
    __shared__ int   bidx[256];

    for (int i = tid; i < SEL; i += 256) vals[i] = cs[h * S_LEN + i];
    float* mrow = mask + h * (S_LEN + 1);
    for (int i = tid; i < S_LEN + 1; i += 256)
        mrow[i] = (i >= (S_LEN + 1 - RB)) ? 1.0f : 0.0f;
    __syncthreads();

    for (int it = 0; it < HB; it++) {
        float best = -INFINITY; int bi = SEL;
        for (int i = tid; i < SEL; i += 256) {
            float v = vals[i];
            if (v > best) { best = v; bi = i; }
        }
        bval[tid] = best; bidx[tid] = bi; __syncthreads();
        for (int s = 128; s > 0; s >>= 1) {
            if (tid < s) {
                if (bval[tid + s] > bval[tid] ||
                    (bval[tid + s] == bval[tid] && bidx[tid + s] < bidx[tid])) {
                    bval[tid] = bval[tid + s];
                    bidx[tid] = bidx[tid + s];
                }
            }
            __syncthreads();
        }
        if (tid == 0) {
            mrow[bidx[0]] = 1.0f;
            vals[bidx[0]] = -INFINITY;
        }
        __syncthreads();
    }
}

// ============================================================================
// Host launcher
// ============================================================================
extern "C" void kernel_launch(void* const* d_in, const int* in_sizes, int n_in,
                              void* d_out, int out_size)
{
    const float* H  = (const float*)d_in[0];
    const float* Wq = (const float*)d_in[1];
    const float* Wk = (const float*)d_in[2];
    const float* Wv = (const float*)d_in[3];
    const float* Wo = (const float*)d_in[4];
    float* out = (float*)d_out;

    float *Q, *K, *V, *Sm, *O, *CS;
    cudaGetSymbolAddress((void**)&Q,  g_Q);
    cudaGetSymbolAddress((void**)&K,  g_K);
    cudaGetSymbolAddress((void**)&V,  g_V);
    cudaGetSymbolAddress((void**)&Sm, g_S);
    cudaGetSymbolAddress((void**)&O,  g_O);
    cudaGetSymbolAddress((void**)&CS, g_CS);

    const float inv_sqrt_hd = 0.08838834764831845f; // 1/sqrt(128)

    // Q, K projections: accurate fp16x2 4-product path (mask-critical)
    gemm_abt4<<<dim3(HID / 128, S_LEN / 128, 1), 256>>>(
        H, Wq, Q, HID, HID, HID, HID, 0, 0, 0, 0, 1.0f, 0);
    gemm_abt4<<<dim3((NKV * HD) / 128, S_LEN / 128, 1), 256>>>(
        H, Wk, K, HID, HID, HID, NKV * HD, 0, 0, 0, 0, 1.0f, 0);
    // V projection: plain fp16 (Output 0 only)
    gemm_abt_f16<<<dim3((NKV * HD) / 128, S_LEN / 128, 1), 256>>>(
        H, Wv, V, HID, HID, HID, NKV * HD, 1.0f);

    // RoPE
    {
        int totQ = S_LEN * NH * 64;
        rope_kernel<<<(totQ + 255) / 256, 256>>>(Q, NH, totQ);
        int totK = S_LEN * NKV * 64;
        rope_kernel<<<(totK + 255) / 256, 256>>>(K, NKV, totK);
    }

    // scores = Q K^T / sqrt(HD): accurate fp16x2 4-product path
    gemm_abt4<<<dim3(S_LEN / 128, S_LEN / 128, NH), 256>>>(
        Q, K, Sm, HD, HID, NKV * HD, S_LEN,
        HD, HD, (long)S_LEN * S_LEN, 2, inv_sqrt_hd, 1);

    // softmax (online; zero-fills diagonal blocks only)
    softmax_causal<<<dim3(S_LEN, NH), 256>>>(Sm);

    // column sums
    colsum_kernel<<<dim3(S_LEN / 256, NH), 256>>>(Sm, CS);

    // context = attn * V : plain fp16
    gemm_ab_f16<<<dim3(HD / 128, S_LEN / 128, NH), 256>>>(
        Sm, V, O, S_LEN, S_LEN, NKV * HD, HID,
        (long)S_LEN * S_LEN, HD, HD, 2, 1.0f, 1);

    // attn_output = O * Wo^T : plain fp16
    gemm_abt_f16<<<dim3(HID / 128, S_LEN / 128, 1), 256>>>(
        O, Wo, out, HID, HID, HID, HID, 1.0f);

    // H2O mask
    {
        size_t maskOff = (size_t)out_size - (size_t)NH * (S_LEN + 1);
        h2o_mask<<<NH, 256>>>(CS, out + maskOff);
    }
}

// round 10
// speedup vs baseline: 2.3162x; 1.0431x over previous
#include <cuda_runtime.h>
#include <cuda_fp16.h>
#include <math.h>
#include <stdint.h>

// ----------------------------------------------------------------------------
// LlamaAttention + H2O mask. fp16 tensor-core GEMMs (m16n8k16):
//   - mask-critical path (Wq, Wk, QK^T): fp16x2 3-product staged split
//     (big+small fp16; aS*bB + aB*bS + aB*bB; the small*small term is below
//     the scheme's residual floor). RN fp32 fold per K=16 chunk.
//   - Output-0-only path (Wv, attn*V, Wo): plain fp16.
// B=1, S=2048, HID=4096, NH=32, NKV=8, HD=128, GROUPS=4, HB=RB=204
// ----------------------------------------------------------------------------

#define S_LEN   2048
#define HID     4096
#define NH      32
#define NKV     8
#define HD      128
#define HB      204
#define RB      204
#define SEL     (S_LEN - RB)   // 1844

__device__ float g_Q [S_LEN * HID];
__device__ float g_K [S_LEN * NKV * HD];
__device__ float g_V [S_LEN * NKV * HD];
__device__ float g_S [(size_t)NH * S_LEN * S_LEN];
__device__ float g_O [S_LEN * HID];
__device__ float g_CS[NH * S_LEN];

// pack two fp32 (consecutive k) into one fp16x2 register (low = even k)
__device__ __forceinline__ uint32_t f2h2(float lo, float hi) {
    __half2 h = __floats2half2_rn(lo, hi);
    return *reinterpret_cast<uint32_t*>(&h);
}

// split-pack: big pair + small (residual) pair
__device__ __forceinline__ void split_pack(float x0, float x1,
                                           uint32_t& bp, uint32_t& sp) {
    __half b0 = __float2half_rn(x0);
    __half b1 = __float2half_rn(x1);
    float r0 = x0 - __half2float(b0);
    float r1 = x1 - __half2float(b1);
    __half2 bb = __halves2half2(b0, b1);
    __half2 ss = __halves2half2(__float2half_rn(r0), __float2half_rn(r1));
    bp = *reinterpret_cast<uint32_t*>(&bb);
    sp = *reinterpret_cast<uint32_t*>(&ss);
}

// D += A*B  (fp16 m16n8k16, fp32 accumulate)
__device__ __forceinline__ void mma_f16(float* c, const uint32_t* a, const uint32_t* b) {
    asm volatile(
        "mma.sync.aligned.m16n8k16.row.col.f32.f16.f16.f32 "
        "{%0,%1,%2,%3}, {%4,%5,%6,%7}, {%8,%9}, {%0,%1,%2,%3};"
        : "+f"(c[0]), "+f"(c[1]), "+f"(c[2]), "+f"(c[3])
        : "r"(a[0]), "r"(a[1]), "r"(a[2]), "r"(a[3]), "r"(b[0]), "r"(b[1]));
}

// D = A*B + 0 (fresh accumulation chain)
__device__ __forceinline__ void mma_f16_zero(float* d, const uint32_t* a, const uint32_t* b) {
    asm volatile(
        "mma.sync.aligned.m16n8k16.row.col.f32.f16.f16.f32 "
        "{%0,%1,%2,%3}, {%4,%5,%6,%7}, {%8,%9}, {%10,%11,%12,%13};"
        : "=f"(d[0]), "=f"(d[1]), "=f"(d[2]), "=f"(d[3])
        : "r"(a[0]), "r"(a[1]), "r"(a[2]), "r"(a[3]), "r"(b[0]), "r"(b[1]),
          "f"(0.0f), "f"(0.0f), "f"(0.0f), "f"(0.0f));
}

// 3-product staged: acc += aS*bB + aB*bS + aB*bB (small*small omitted;
// it is <= 2^-22 relative, below the split-residual floor).
__device__ __forceinline__ void mma3_staged(float* acc,
                                            const uint32_t* aB, const uint32_t* aS,
                                            const uint32_t* bB, const uint32_t* bS) {
    float tmp[4];
    mma_f16_zero(tmp, aS, bB);
    mma_f16(tmp, aB, bS);
    mma_f16(tmp, aB, bB);
    acc[0] += tmp[0];
    acc[1] += tmp[1];
    acc[2] += tmp[2];
    acc[3] += tmp[3];
}

// ============================================================================
// fp16x2 3-product GEMM: C = alpha * A * B^T   (mask-critical path)
// A: M x K row-major, B: N x K row-major, C: M x N row-major.
// grid (N/128, M/128, heads). causal=1: skip blocks bx > by.
// ============================================================================
__global__ __launch_bounds__(256)
void gemm_abt3h(const float* __restrict__ A, const float* __restrict__ B,
                float* __restrict__ C,
                int K, int lda, int ldb, int ldc,
                long aHS, long bHS, long cHS, int bShift,
                float alpha, int causal)
{
    const int h = blockIdx.z;
    A += (long)h * aHS;
    B += (long)(h >> bShift) * bHS;
    C += (long)h * cHS;
    const int bx = blockIdx.x, by = blockIdx.y;
    if (causal && bx > by) return;

    __shared__ uint32_t AsB[8][132];
    __shared__ uint32_t AsS[8][132];
    __shared__ uint32_t BsB[8][132];
    __shared__ uint32_t BsS[8][132];

    const int tid  = threadIdx.x;
    const int lane = tid & 31;
    const int wid  = tid >> 5;
    const int g    = lane >> 2;
    const int tig  = lane & 3;
    const int mbase = (wid >> 2) * 64;
    const int nbase = (wid & 3) * 32;

    const int lrow = tid >> 2;           // 0..63 (+64)
    const int lcol = (tid & 3) * 4;      // k offset 0,4,8,12
    const int kp0  = lcol >> 1;          // k-pair row 0,2,4,6

    const float* Ab = A + (long)(by * 128) * lda;
    const float* Bb = B + (long)(bx * 128) * ldb;

    float acc[4][4][4];
#pragma unroll
    for (int i = 0; i < 4; i++)
#pragma unroll
        for (int j = 0; j < 4; j++)
#pragma unroll
            for (int k = 0; k < 4; k++) acc[i][j][k] = 0.0f;

    float4 ra[2], rb[2];
#pragma unroll
    for (int r = 0; r < 2; r++) {
        ra[r] = *(const float4*)(Ab + (long)(lrow + r * 64) * lda + lcol);
        rb[r] = *(const float4*)(Bb + (long)(lrow + r * 64) * ldb + lcol);
    }

    for (int kk = 0; kk < K; kk += 16) {
#pragma unroll
        for (int r = 0; r < 2; r++) {
            const int row = lrow + r * 64;
            split_pack(ra[r].x, ra[r].y, AsB[kp0    ][row], AsS[kp0    ][row]);
            split_pack(ra[r].z, ra[r].w, AsB[kp0 + 1][row], AsS[kp0 + 1][row]);
            split_pack(rb[r].x, rb[r].y, BsB[kp0    ][row], BsS[kp0    ][row]);
            split_pack(rb[r].z, rb[r].w, BsB[kp0 + 1][row], BsS[kp0 + 1][row]);
        }
        __syncthreads();

        if (kk + 16 < K) {
#pragma unroll
            for (int r = 0; r < 2; r++) {
                ra[r] = *(const float4*)(Ab + (long)(lrow + r * 64) * lda + kk + 16 + lcol);
                rb[r] = *(const float4*)(Bb + (long)(lrow + r * 64) * ldb + kk + 16 + lcol);
            }
        }

        {
            uint32_t afB[4][4], afS[4][4], bfB[4][2], bfS[4][2];
#pragma unroll
            for (int mt = 0; mt < 4; mt++) {
                const int r0 = mbase + mt * 16 + g;
                afB[mt][0] = AsB[tig    ][r0    ];
                afB[mt][1] = AsB[tig    ][r0 + 8];
                afB[mt][2] = AsB[tig + 4][r0    ];
                afB[mt][3] = AsB[tig + 4][r0 + 8];
                afS[mt][0] = AsS[tig    ][r0    ];
                afS[mt][1] = AsS[tig    ][r0 + 8];
                afS[mt][2] = AsS[tig + 4][r0    ];
                afS[mt][3] = AsS[tig + 4][r0 + 8];
            }
#pragma unroll
            for (int nt = 0; nt < 4; nt++) {
                const int c0 = nbase + nt * 8 + g;
                bfB[nt][0] = BsB[tig    ][c0];
                bfB[nt][1] = BsB[tig + 4][c0];
                bfS[nt][0] = BsS[tig    ][c0];
                bfS[nt][1] = BsS[tig + 4][c0];
            }
#pragma unroll
            for (int mt = 0; mt < 4; mt++)
#pragma unroll
                for (int nt = 0; nt < 4; nt++)
                    mma3_staged(acc[mt][nt], afB[mt], afS[mt], bfB[nt], bfS[nt]);
        }
        __syncthreads();
    }

#pragma unroll
    for (int mt = 0; mt < 4; mt++) {
#pragma unroll
        for (int nt = 0; nt < 4; nt++) {
            const int row0 = by * 128 + mbase + mt * 16 + g;
            const int col0 = bx * 128 + nbase + nt * 8 + 2 * tig;
            C[(long)row0 * ldc + col0    ] = alpha * acc[mt][nt][0];
            C[(long)row0 * ldc + col0 + 1] = alpha * acc[mt][nt][1];
            C[(long)(row0 + 8) * ldc + col0    ] = alpha * acc[mt][nt][2];
            C[(long)(row0 + 8) * ldc + col0 + 1] = alpha * acc[mt][nt][3];
        }
    }
}

// ============================================================================
// Plain fp16 GEMM: C = alpha * A * B^T  (Wv, Wo projections; Output 0 only)
// ============================================================================
__global__ __launch_bounds__(256)
void gemm_abt_f16(const float* __restrict__ A, const float* __restrict__ B,
                  float* __restrict__ C,
                  int K, int lda, int ldb, int ldc, float alpha)
{
    const int bx = blockIdx.x, by = blockIdx.y;

    __shared__ uint32_t As[8][132];
    __shared__ uint32_t Bs[8][132];

    const int tid  = threadIdx.x;
    const int lane = tid & 31;
    const int wid  = tid >> 5;
    const int g    = lane >> 2;
    const int tig  = lane & 3;
    const int mbase = (wid >> 2) * 64;
    const int nbase = (wid & 3) * 32;

    const int lrow = tid >> 2;
    const int lcol = (tid & 3) * 4;
    const int kp0  = lcol >> 1;

    const float* Ab = A + (long)(by * 128) * lda;
    const float* Bb = B + (long)(bx * 128) * ldb;

    float acc[4][4][4];
#pragma unroll
    for (int i = 0; i < 4; i++)
#pragma unroll
        for (int j = 0; j < 4; j++)
#pragma unroll
            for (int k = 0; k < 4; k++) acc[i][j][k] = 0.0f;

    float4 ra[2], rb[2];
#pragma unroll
    for (int r = 0; r < 2; r++) {
        ra[r] = *(const float4*)(Ab + (long)(lrow + r * 64) * lda + lcol);
        rb[r] = *(const float4*)(Bb + (long)(lrow + r * 64) * ldb + lcol);
    }

    for (int kk = 0; kk < K; kk += 16) {
#pragma unroll
        for (int r = 0; r < 2; r++) {
            const int row = lrow + r * 64;
            As[kp0    ][row] = f2h2(ra[r].x, ra[r].y);
            As[kp0 + 1][row] = f2h2(ra[r].z, ra[r].w);
            Bs[kp0    ][row] = f2h2(rb[r].x, rb[r].y);
            Bs[kp0 + 1][row] = f2h2(rb[r].z, rb[r].w);
        }
        __syncthreads();

        if (kk + 16 < K) {
#pragma unroll
            for (int r = 0; r < 2; r++) {
                ra[r] = *(const float4*)(Ab + (long)(lrow + r * 64) * lda + kk + 16 + lcol);
                rb[r] = *(const float4*)(Bb + (long)(lrow + r * 64) * ldb + kk + 16 + lcol);
            }
        }

        {
            uint32_t af[4][4], bf[4][2];
#pragma unroll
            for (int mt = 0; mt < 4; mt++) {
                const int r0 = mbase + mt * 16 + g;
                af[mt][0] = As[tig    ][r0    ];
                af[mt][1] = As[tig    ][r0 + 8];
                af[mt][2] = As[tig + 4][r0    ];
                af[mt][3] = As[tig + 4][r0 + 8];
            }
#pragma unroll
            for (int nt = 0; nt < 4; nt++) {
                const int c0 = nbase + nt * 8 + g;
                bf[nt][0] = Bs[tig    ][c0];
                bf[nt][1] = Bs[tig + 4][c0];
            }
#pragma unroll
            for (int mt = 0; mt < 4; mt++)
#pragma unroll
                for (int nt = 0; nt < 4; nt++)
                    mma_f16(acc[mt][nt], af[mt], bf[nt]);
        }
        __syncthreads();
    }

#pragma unroll
    for (int mt = 0; mt < 4; mt++) {
#pragma unroll
        for (int nt = 0; nt < 4; nt++) {
            const int row0 = by * 128 + mbase + mt * 16 + g;
            const int col0 = bx * 128 + nbase + nt * 8 + 2 * tig;
            C[(long)row0 * ldc + col0    ] = alpha * acc[mt][nt][0];
            C[(long)row0 * ldc + col0 + 1] = alpha * acc[mt][nt][1];
            C[(long)(row0 + 8) * ldc + col0    ] = alpha * acc[mt][nt][2];
            C[(long)(row0 + 8) * ldc + col0 + 1] = alpha * acc[mt][nt][3];
        }
    }
}

// ============================================================================
// Plain fp16 GEMM: C = alpha * A * B  (attn * V, per-head; B row-major K x N)
// causal=1: limit K to (by+1)*128. B packed vertically (k-pairs).
// ============================================================================
__global__ __launch_bounds__(256)
void gemm_ab_f16(const float* __restrict__ A, const float* __restrict__ B,
                 float* __restrict__ C,
                 int K, int lda, int ldb, int ldc,
                 long aHS, long bHS, long cHS, int bShift,
                 float alpha, int causal)
{
    const int h = blockIdx.z;
    A += (long)h * aHS;
    B += (long)(h >> bShift) * bHS;
    C += (long)h * cHS;
    const int bx = blockIdx.x, by = blockIdx.y;

    __shared__ uint32_t As[8][132];
    __shared__ uint32_t Bs[8][132];

    const int tid  = threadIdx.x;
    const int lane = tid & 31;
    const int wid  = tid >> 5;
    const int g    = lane >> 2;
    const int tig  = lane & 3;
    const int mbase = (wid >> 2) * 64;
    const int nbase = (wid & 3) * 32;

    const int lrow  = tid >> 2;
    const int lcol  = (tid & 3) * 4;
    const int kp0   = lcol >> 1;
    const int brow  = tid >> 5;          // k-pair row 0..7
    const int bcol4 = (tid & 31) * 4;

    const float* Ab = A + (long)(by * 128) * lda;

    const int Keff = causal ? (((by + 1) * 128 < K) ? (by + 1) * 128 : K) : K;

    float acc[4][4][4];
#pragma unroll
    for (int i = 0; i < 4; i++)
#pragma unroll
        for (int j = 0; j < 4; j++)
#pragma unroll
            for (int k = 0; k < 4; k++) acc[i][j][k] = 0.0f;

    float4 ra[2], rbl, rbh;
#pragma unroll
    for (int r = 0; r < 2; r++)
        ra[r] = *(const float4*)(Ab + (long)(lrow + r * 64) * lda + lcol);
    rbl = *(const float4*)(B + (long)(2 * brow    ) * ldb + bx * 128 + bcol4);
    rbh = *(const float4*)(B + (long)(2 * brow + 1) * ldb + bx * 128 + bcol4);

    for (int kk = 0; kk < Keff; kk += 16) {
#pragma unroll
        for (int r = 0; r < 2; r++) {
            const int row = lrow + r * 64;
            As[kp0    ][row] = f2h2(ra[r].x, ra[r].y);
            As[kp0 + 1][row] = f2h2(ra[r].z, ra[r].w);
        }
        Bs[brow][bcol4 + 0] = f2h2(rbl.x, rbh.x);
        Bs[brow][bcol4 + 1] = f2h2(rbl.y, rbh.y);
        Bs[brow][bcol4 + 2] = f2h2(rbl.z, rbh.z);
        Bs[brow][bcol4 + 3] = f2h2(rbl.w, rbh.w);
        __syncthreads();

        if (kk + 16 < Keff) {
#pragma unroll
            for (int r = 0; r < 2; r++)
                ra[r] = *(const float4*)(Ab + (long)(lrow + r * 64) * lda + kk + 16 + lcol);
            rbl = *(const float4*)(B + (long)(kk + 16 + 2 * brow    ) * ldb + bx * 128 + bcol4);
            rbh = *(const float4*)(B + (long)(kk + 16 + 2 * brow + 1) * ldb + bx * 128 + bcol4);
        }

        {
            uint32_t af[4][4], bf[4][2];
#pragma unroll
            for (int mt = 0; mt < 4; mt++) {
                const int r0 = mbase + mt * 16 + g;
                af[mt][0] = As[tig    ][r0    ];
                af[mt][1] = As[tig    ][r0 + 8];
                af[mt][2] = As[tig + 4][r0    ];
                af[mt][3] = As[tig + 4][r0 + 8];
            }
#pragma unroll
            for (int nt = 0; nt < 4; nt++) {
                const int c0 = nbase + nt * 8 + g;
                bf[nt][0] = Bs[tig    ][c0];
                bf[nt][1] = Bs[tig + 4][c0];
            }
#pragma unroll
            for (int mt = 0; mt < 4; mt++)
#pragma unroll
                for (int nt = 0; nt < 4; nt++)
                    mma_f16(acc[mt][nt], af[mt], bf[nt]);
        }
        __syncthreads();
    }

#pragma unroll
    for (int mt = 0; mt < 4; mt++) {
#pragma unroll
        for (int nt = 0; nt < 4; nt++) {
            const int row0 = by * 128 + mbase + mt * 16 + g;
            const int col0 = bx * 128 + nbase + nt * 8 + 2 * tig;
            C[(long)row0 * ldc + col0    ] = alpha * acc[mt][nt][0];
            C[(long)row0 * ldc + col0 + 1] = alpha * acc[mt][nt][1];
            C[(long)(row0 + 8) * ldc + col0    ] = alpha * acc[mt][nt][2];
            C[(long)(row0 + 8) * ldc + col0 + 1] = alpha * acc[mt][nt][3];
        }
    }
}

// ============================================================================
// RoPE in place. X: [S, nh*HD]. One thread per (s, h, d<64).
// ============================================================================
__global__ void rope_kernel(float* __restrict__ X, int nh, int total)
{
    int idx = blockIdx.x * blockDim.x + threadIdx.x;
    if (idx >= total) return;
    int d = idx & 63;
    int h = (idx >> 6) % nh;
    int s = idx / (64 * nh);
    float e    = (float)(2 * d) * (1.0f / 128.0f);
    float invf = 1.0f / powf(10000.0f, e);
    float ang  = (float)s * invf;
    float c = cosf(ang), sn = sinf(ang);
    float* p = X + (long)s * (nh * HD) + h * HD;
    float x1 = p[d], x2 = p[d + 64];
    p[d]      = x1 * c - x2 * sn;
    p[d + 64] = x2 * c + x1 * sn;
}

// ============================================================================
// Causal row softmax, online max/sum; zero-fills diagonal block only.
// ============================================================================
__global__ __launch_bounds__(256)
void softmax_causal(float* __restrict__ Sm)
{
    const int q = blockIdx.x, h = blockIdx.y;
    float* row = Sm + ((long)h * S_LEN + q) * S_LEN;
    const int len = q + 1;
    const int tid = threadIdx.x;
    __shared__ float mred[256], sred[256];

    float m = -INFINITY, s = 0.0f;
    for (int i = tid; i < len; i += 256) {
        float x = row[i];
        float nm = fmaxf(m, x);
        s = s * expf(m - nm) + expf(x - nm);
        m = nm;
    }
    mred[tid] = m; sred[tid] = s; __syncthreads();
    for (int st = 128; st > 0; st >>= 1) {
        if (tid < st) {
            float m1 = mred[tid], s1 = sred[tid];
            float m2 = mred[tid + st], s2 = sred[tid + st];
            float nm = fmaxf(m1, m2);
            float sm = 0.0f;
            if (m1 > -INFINITY) sm += s1 * expf(m1 - nm);
            if (m2 > -INFINITY) sm += s2 * expf(m2 - nm);
            mred[tid] = nm; sred[tid] = sm;
        }
        __syncthreads();
    }
    const float M = mred[0];
    const float inv = 1.0f / sred[0];

    for (int i = tid; i < len; i += 256) row[i] = expf(row[i] - M) * inv;

    const int fillEnd = ((q >> 7) + 1) << 7;
    for (int i = len + tid; i < fillEnd; i += 256) row[i] = 0.0f;
}

// ============================================================================
// Column sums: cs[h][k] = sum_q attn[h][q][k] (lower triangle only).
// ============================================================================
__global__ __launch_bounds__(256)
void colsum_kernel(const float* __restrict__ attn, float* __restrict__ cs)
{
    const int k = blockIdx.x * 256 + threadIdx.x;
    const int h = blockIdx.y;
    const float* base = attn + (size_t)h * S_LEN * S_LEN;
    float s = 0.0f;
    for (int q = k; q < S_LEN; q++) s += base[(long)q * S_LEN + k];
    cs[h * S_LEN + k] = s;
}

// ============================================================================
// H2O mask: per head top-HB of colsum[0:SEL] + last RB columns.
// ============================================================================
__global__ __launch_bounds__(256)
void h2o_mask(const float* __restrict__ cs, float* __restrict__ mask)
{
    const int h = blockIdx.x;
    const int tid = threadIdx.x;
    __shared__ float vals[SEL];
    __shared__ float bval[256];
    __shared__ int   bidx[256];

    for (int i = tid; i < SEL; i += 256) vals[i] = cs[h * S_LEN + i];
    float* mrow = mask + h * (S_LEN + 1);
    for (int i = tid; i < S_LEN + 1; i += 256)
        mrow[i] = (i >= (S_LEN + 1 - RB)) ? 1.0f : 0.0f;
    __syncthreads();

    for (int it = 0; it < HB; it++) {
        float best = -INFINITY; int bi = SEL;
        for (int i = tid; i < SEL; i += 256) {
            float v = vals[i];
            if (v > best) { best = v; bi = i; }
        }
        bval[tid] = best; bidx[tid] = bi; __syncthreads();
        for (int s = 128; s > 0; s >>= 1) {
            if (tid < s) {
                if (bval[tid + s] > bval[tid] ||
                    (bval[tid + s] == bval[tid] && bidx[tid + s] < bidx[tid])) {
                    bval[tid] = bval[tid + s];
                    bidx[tid] = bidx[tid + s];
                }
            }
            __syncthreads();
        }
        if (tid == 0) {
            mrow[bidx[0]] = 1.0f;
            vals[bidx[0]] = -INFINITY;
        }
        __syncthreads();
    }
}

// ============================================================================
// Host launcher
// ============================================================================
extern "C" void kernel_launch(void* const* d_in, const int* in_sizes, int n_in,
                              void* d_out, int out_size)
{
    const float* H  = (const float*)d_in[0];
    const float* Wq = (const float*)d_in[1];
    const float* Wk = (const float*)d_in[2];
    const float* Wv = (const float*)d_in[3];
    const float* Wo = (const float*)d_in[4];
    float* out = (float*)d_out;

    float *Q, *K, *V, *Sm, *O, *CS;
    cudaGetSymbolAddress((void**)&Q,  g_Q);
    cudaGetSymbolAddress((void**)&K,  g_K);
    cudaGetSymbolAddress((void**)&V,  g_V);
    cudaGetSymbolAddress((void**)&Sm, g_S);
    cudaGetSymbolAddress((void**)&O,  g_O);
    cudaGetSymbolAddress((void**)&CS, g_CS);

    const float inv_sqrt_hd = 0.08838834764831845f; // 1/sqrt(128)

    // Q, K projections: fp16x2 3-product path (mask-critical)
    gemm_abt3h<<<dim3(HID / 128, S_LEN / 128, 1), 256>>>(
        H, Wq, Q, HID, HID, HID, HID, 0, 0, 0, 0, 1.0f, 0);
    gemm_abt3h<<<dim3((NKV * HD) / 128, S_LEN / 128, 1), 256>>>(
        H, Wk, K, HID, HID, HID, NKV * HD, 0, 0, 0, 0, 1.0f, 0);
    // V projection: plain fp16 (Output 0 only)
    gemm_abt_f16<<<dim3((NKV * HD) / 128, S_LEN / 128, 1), 256>>>(
        H, Wv, V, HID, HID, HID, NKV * HD, 1.0f);

    // RoPE
    {
        int totQ = S_LEN * NH * 64;
        rope_kernel<<<(totQ + 255) / 256, 256>>>(Q, NH, totQ);
        int totK = S_LEN * NKV * 64;
        rope_kernel<<<(totK + 255) / 256, 256>>>(K, NKV, totK);
    }

    // scores = Q K^T / sqrt(HD): fp16x2 3-product path
    gemm_abt3h<<<dim3(S_LEN / 128, S_LEN / 128, NH), 256>>>(
        Q, K, Sm, HD, HID, NKV * HD, S_LEN,
        HD, HD, (long)S_LEN * S_LEN, 2, inv_sqrt_hd, 1);

    // softmax (online; zero-fills diagonal blocks only)
    softmax_causal<<<dim3(S_LEN, NH), 256>>>(Sm);

    // column sums
    colsum_kernel<<<dim3(S_LEN / 256, NH), 256>>>(Sm, CS);

    // context = attn * V : plain fp16
    gemm_ab_f16<<<dim3(HD / 128, S_LEN / 128, NH), 256>>>(
        Sm, V, O, S_LEN, S_LEN, NKV * HD, HID,
        (long)S_LEN * S_LEN, HD, HD, 2, 1.0f, 1);

    // attn_output = O * Wo^T : plain fp16
    gemm_abt_f16<<<dim3(HID / 128, S_LEN / 128, 1), 256>>>(
        O, Wo, out, HID, HID, HID, HID, 1.0f);

    // H2O mask
    {
        size_t maskOff = (size_t)out_size - (size_t)NH * (S_LEN + 1);
        h2o_mask<<<NH, 256>>>(CS, out + maskOff);
    }
}